// round 6
// baseline (speedup 1.0000x reference)
#include <cuda_runtime.h>
#include <math.h>
#include <mma.h>

using namespace nvcuda;

#define Hq   4
#define Lq   4096
#define Dq   1024
#define CHK  32
#define NCHK 128
#define MROWS 16384

// ---------------- scratch arena (no cudaMalloc allowed) ----------------
constexpr size_t SZf      = 16777216ull;            // 16384*1024
constexpr size_t OFF_QPRE = 0;                      // reused later as U
constexpr size_t OFF_U    = 0;
constexpr size_t OFF_KPRE = SZf;                    // reused later as W
constexpr size_t OFF_W    = SZf;
constexpr size_t OFF_VPRE = 2*SZf;                  // reused later as DELTA_O
constexpr size_t OFF_DELTA= 2*SZf;
constexpr size_t OFF_Q    = 3*SZf;
constexpr size_t OFF_K    = 4*SZf;
constexpr size_t OFF_V    = 5*SZf;
constexpr size_t OFF_EMAS = 6*SZf;
constexpr size_t OFF_EMAL = 7*SZf;
constexpr size_t OFF_OMIX = 8*SZf;
constexpr size_t OFF_Z    = 9*SZf;                  // 16384*512
constexpr size_t OFF_ATTN = OFF_Z + 8388608ull;     // 2048*1024
constexpr size_t OFF_BETA = OFF_ATTN + 2097152ull;  // 65536
constexpr size_t OFF_GS   = OFF_BETA + 65536ull;
constexpr size_t OFF_GL   = OFF_GS + 65536ull;
constexpr size_t OFF_WGT  = OFF_GL + 65536ull;      // 16384*16
constexpr size_t ARENA_TOTAL = OFF_WGT + 262144ull;

__device__ float g_arena[ARENA_TOTAL];

constexpr int PRE_SMEM_BYTES  = 26816 * 4;   // 107264

// wmma scan smem: S, Shi, Slo (256x36) + uh, uhh, uhl (32x36)
constexpr int SLD = 36;
constexpr int SCAN_SMEM_FLOATS = 3*256*SLD + 3*32*SLD;  // 31104
constexpr int SCAN_SMEM_BYTES  = SCAN_SMEM_FLOATS * 4;  // 124416

// GEMM tiling: 128x128 tile, BK=32, 3-stage pipeline
constexpr int GBM = 128, GBN = 128, GBK = 32, GAP = 36;
constexpr int GSTAGE = (GBM+GBN)*GAP;            // 9216 floats per stage
constexpr int GEMM_SMEM_BYTES = 3*GSTAGE*4;      // 110592
constexpr int CLD = 132;                         // epilogue ld

__device__ __forceinline__ float sigm(float x){ return 1.f/(1.f+expf(-x)); }
__device__ __forceinline__ float silu(float x){ return x/(1.f+expf(-x)); }

__device__ __forceinline__ float warp_sum(float v){
    #pragma unroll
    for (int o=16;o>0;o>>=1) v += __shfl_xor_sync(0xffffffffu, v, o);
    return v;
}

__device__ __forceinline__ void cp16(float* s, const float* g){
    unsigned a = (unsigned)__cvta_generic_to_shared(s);
    asm volatile("cp.async.cg.shared.global [%0], [%1], 16;" :: "r"(a), "l"(g));
}

// ---------------- TF32 tensor-core GEMM: C[M,N] = A[M,K] @ W[N,K]^T ----------
// 128x128 tile, 3-stage cp.async, 8 warps each 32x64 (2x4 frags)
__global__ void gemm_tf32_kernel(const float* __restrict__ A, const float* __restrict__ W,
                                 const float* __restrict__ bias, float* __restrict__ C,
                                 int M, int N, int K, int act)
{
    extern __shared__ float smem[];
    const int tid = threadIdx.x, warp = tid>>5;
    const int m0 = blockIdx.y*GBM, n0 = blockIdx.x*GBN;
    const int wr = warp>>1, wc = warp&1;
    const int lr = tid>>3, lc = (tid&7)*4;

    wmma::fragment<wmma::accumulator,16,16,8,float> acc[2][4];
    #pragma unroll
    for(int i=0;i<2;i++)
        #pragma unroll
        for(int j=0;j<4;j++) wmma::fill_fragment(acc[i][j], 0.f);

    const int KT = K/GBK;

    auto load_stage = [&](int it){
        float* As = smem + (it%3)*GSTAGE;
        float* Ws = As + GBM*GAP;
        const int k0 = it*GBK;
        #pragma unroll
        for (int s=0;s<4;s++){
            int r = lr + s*32;
            cp16(&As[r*GAP+lc], &A[(size_t)(m0+r)*K + k0 + lc]);
        }
        #pragma unroll
        for (int s=0;s<4;s++){
            int r = lr + s*32;
            cp16(&Ws[r*GAP+lc], &W[(size_t)(n0+r)*K + k0 + lc]);
        }
        asm volatile("cp.async.commit_group;");
    };

    load_stage(0);
    load_stage(1);

    for (int it=0; it<KT; ++it){
        if (it+2 < KT){
            load_stage(it+2);
            asm volatile("cp.async.wait_group 2;");
        } else if (it+1 < KT){
            asm volatile("cp.async.wait_group 1;");
        } else {
            asm volatile("cp.async.wait_group 0;");
        }
        __syncthreads();

        float* As = smem + (it%3)*GSTAGE;
        float* Ws = As + GBM*GAP;
        #pragma unroll
        for (int kk=0; kk<GBK; kk+=8){
            wmma::fragment<wmma::matrix_a,16,16,8,wmma::precision::tf32,wmma::row_major> af[2];
            wmma::fragment<wmma::matrix_b,16,16,8,wmma::precision::tf32,wmma::col_major> bf[4];
            #pragma unroll
            for (int i=0;i<2;i++){
                wmma::load_matrix_sync(af[i], &As[(wr*32+i*16)*GAP + kk], GAP);
                #pragma unroll
                for (int t=0;t<af[i].num_elements;t++) af[i].x[t] = wmma::__float_to_tf32(af[i].x[t]);
            }
            #pragma unroll
            for (int j=0;j<4;j++){
                wmma::load_matrix_sync(bf[j], &Ws[(wc*64+j*16)*GAP + kk], GAP);
                #pragma unroll
                for (int t=0;t<bf[j].num_elements;t++) bf[j].x[t] = wmma::__float_to_tf32(bf[j].x[t]);
            }
            #pragma unroll
            for (int i=0;i<2;i++)
                #pragma unroll
                for (int j=0;j<4;j++)
                    wmma::mma_sync(acc[i][j], af[i], bf[j], acc[i][j]);
        }
        __syncthreads();
    }

    // epilogue via smem (bias / silu)
    float* Cs = smem;   // [128][132]
    #pragma unroll
    for (int i=0;i<2;i++)
        #pragma unroll
        for (int j=0;j<4;j++)
            wmma::store_matrix_sync(&Cs[(wr*32+i*16)*CLD + wc*64 + j*16], acc[i][j], CLD, wmma::mem_row_major);
    __syncthreads();

    for (int idx = tid; idx < GBM*GBN/4; idx += 256){
        int row = idx >> 5, col = (idx & 31)*4;
        float4 v4 = *reinterpret_cast<float4*>(&Cs[row*CLD + col]);
        float* vv = (float*)&v4;
        #pragma unroll
        for (int j=0;j<4;j++){
            float v = vv[j];
            if (bias) v += bias[n0+col+j];
            if (act==1) v = v/(1.f+expf(-v));
            vv[j] = v;
        }
        *reinterpret_cast<float4*>(&C[(size_t)(m0+row)*N + n0+col]) = v4;
    }
}

// ---------------- causal depthwise conv (k=4) + SiLU, relayout to head-major ----
__global__ void conv_silu_kernel(const float* __restrict__ qp, const float* __restrict__ kp,
                                 const float* __restrict__ vp,
                                 const float* __restrict__ wq, const float* __restrict__ wk,
                                 const float* __restrict__ wv,
                                 float* __restrict__ qo, float* __restrict__ ko,
                                 float* __restrict__ vo)
{
    const int row = blockIdx.x;                 // b*L + l
    const int d   = blockIdx.y*256 + threadIdx.x;
    const int l = row & (Lq-1), b = row >> 12;
    const int h = d >> 8, dk = d & 255;
    float aq=0.f, ak=0.f, av=0.f;
    #pragma unroll
    for (int j=0;j<4;j++){
        int ls = l - 3 + j;
        if (ls >= 0){
            size_t idx = (size_t)(row - 3 + j)*Dq + d;
            aq = fmaf(qp[idx], wq[d*4+j], aq);
            ak = fmaf(kp[idx], wk[d*4+j], ak);
            av = fmaf(vp[idx], wv[d*4+j], av);
        }
    }
    size_t o = ((size_t)(b*Hq + h)*Lq + l)*256 + dk;
    qo[o] = silu(aq);
    ko[o] = silu(ak);
    vo[o] = silu(av);
}

// ---------------- beta / g_s / g_l projections ----------------
__global__ void smallproj_kernel(const float* __restrict__ x,
                                 const float* __restrict__ Wb, const float* __restrict__ Wds,
                                 const float* __restrict__ bds, const float* __restrict__ Wdl,
                                 const float* __restrict__ bdl,
                                 float* __restrict__ beta, float* __restrict__ gs,
                                 float* __restrict__ gl)
{
    const int row = blockIdx.x;
    const float* xr = x + (size_t)row*Dq;
    float acc[12];
    #pragma unroll
    for (int r=0;r<12;r++) acc[r]=0.f;
    for (int j=threadIdx.x;j<Dq;j+=256){
        const float xv = xr[j];
        #pragma unroll
        for (int h=0;h<4;h++){
            acc[h]   = fmaf(xv, Wb [h*Dq+j], acc[h]);
            acc[4+h] = fmaf(xv, Wds[h*Dq+j], acc[4+h]);
            acc[8+h] = fmaf(xv, Wdl[h*Dq+j], acc[8+h]);
        }
    }
    __shared__ float red[12][9];
    const int lane = threadIdx.x & 31, w = threadIdx.x >> 5;
    #pragma unroll
    for (int r=0;r<12;r++){
        float s = warp_sum(acc[r]);
        if (lane==0) red[r][w] = s;
    }
    __syncthreads();
    if (threadIdx.x < 12){
        float s = 0.f;
        #pragma unroll
        for (int ww=0;ww<8;ww++) s += red[threadIdx.x][ww];
        const int h = threadIdx.x & 3;
        const int b = row >> 12, l = row & (Lq-1);
        size_t o = (size_t)(b*4 + h)*Lq + l;
        if (threadIdx.x < 4)      beta[o] = sigm(s);
        else if (threadIdx.x < 8) gs[o]   = sigm(s + bds[h]);
        else                      gl[o]   = sigm(s + bdl[h]);
    }
}

// ---------------- delta-rule per-chunk precompute ----------------
__global__ void chunk_pre_kernel(float* __restrict__ q, float* __restrict__ k,
                                 const float* __restrict__ v, const float* __restrict__ beta,
                                 float* __restrict__ u, float* __restrict__ w,
                                 float* __restrict__ attn)
{
    extern __shared__ float sm[];
    float* qs = sm;              // 32*257
    float* ks = qs + 8224;
    float* vs = ks + 8224;
    float* Lm = vs + 8224;       // 32*33
    float* Ti = Lm + 1056;       // 32*33
    float* bs = Ti + 1056;       // 32
    const int bh = blockIdx.x >> 7;
    const int c  = blockIdx.x & 127;
    const int tid = threadIdx.x, lane = tid&31, wid = tid>>5;
    const size_t base = (size_t)bh*Lq + (size_t)c*CHK;

    for (int idx = tid; idx < 32*256; idx += 256){
        int i = idx >> 8, d = idx & 255;
        size_t g = (base + i)*256 + d;
        qs[i*257+d] = q[g];
        ks[i*257+d] = k[g];
        vs[i*257+d] = v[g];
    }
    if (tid < 32) bs[tid] = beta[base + tid];
    __syncthreads();

    #pragma unroll
    for (int r=0;r<4;r++){
        int i = wid*4 + r;
        float sq=0.f, sk=0.f;
        for (int d=lane; d<256; d+=32){
            float a=qs[i*257+d]; sq=fmaf(a,a,sq);
            float bb=ks[i*257+d]; sk=fmaf(bb,bb,sk);
        }
        sq = warp_sum(sq); sk = warp_sum(sk);
        float rq = rsqrtf(sq + 1e-6f), rk = rsqrtf(sk + 1e-6f);
        for (int d=lane; d<256; d+=32){ qs[i*257+d]*=rq; ks[i*257+d]*=rk; }
    }
    __syncthreads();

    for (int idx = tid; idx < 32*256; idx += 256){
        int i = idx>>8, d = idx&255;
        size_t g = (base+i)*256 + d;
        q[g] = qs[i*257+d];
        k[g] = ks[i*257+d];
        vs[i*257+d] *= bs[i];
    }
    __syncthreads();

    #pragma unroll
    for (int r=0;r<4;r++){
        int i = wid + 8*r;
        float aq=0.f, akk=0.f;
        for (int d=0; d<256; d++){
            float kjd = ks[lane*257+d];
            aq  = fmaf(qs[i*257+d], kjd, aq);
            akk = fmaf(ks[i*257+d], kjd, akk);
        }
        Lm[i*33+lane] = (lane < i) ? bs[i]*akk : 0.f;
        attn[(size_t)blockIdx.x*1024 + i*32 + lane] = (lane <= i) ? aq : 0.f;
    }
    __syncthreads();

    if (wid == 0){
        for (int i=0;i<32;i++){
            float xv = (lane==i) ? 1.f : 0.f;
            for (int p=0;p<i;p++) xv = fmaf(-Lm[i*33+p], Ti[p*33+lane], xv);
            Ti[i*33+lane] = xv;
            __syncwarp();
        }
    }
    __syncthreads();

    for (int idx = tid; idx < 1024; idx += 256){
        int i = idx>>5, j = idx&31;
        Lm[i*33+j] = Ti[i*33+j]*bs[j];
    }
    __syncthreads();

    #pragma unroll
    for (int r=0;r<4;r++){
        int i = wid + 8*r;
        #pragma unroll
        for (int m=0;m<8;m++){
            int d = lane + 32*m;
            float au=0.f, aw=0.f;
            #pragma unroll
            for (int j=0;j<32;j++){
                au = fmaf(Ti[i*33+j], vs[j*257+d], au);
                aw = fmaf(Lm[i*33+j], ks[j*257+d], aw);
            }
            size_t g = (base+i)*256 + d;
            u[g] = au;
            w[g] = aw;
        }
    }
}

// ---------------- delta-rule inter-chunk scan (TF32 wmma, split-precision S) ----
__global__ void scan_kernel(const float* __restrict__ q, const float* __restrict__ k,
                            const float* __restrict__ u, const float* __restrict__ w,
                            const float* __restrict__ attn, float* __restrict__ o)
{
    extern __shared__ float sm[];
    float* S   = sm;                  // 256*36 fp32 master
    float* Shi = S   + 256*SLD;       // tf32-exact high part
    float* Slo = Shi + 256*SLD;       // tf32 residual
    float* uh  = Slo + 256*SLD;       // 32*36 fp32
    float* uhh = uh  + 32*SLD;
    float* uhl = uhh + 32*SLD;
    const int bh = blockIdx.x >> 3;
    const int d0 = (blockIdx.x & 7) * 32;
    const int tid = threadIdx.x, warp = tid >> 5;

    for (int i = tid; i < 3*256*SLD; i += 256) sm[i] = 0.f;
    __syncthreads();

    wmma::fragment<wmma::accumulator,16,16,8,float> acc2;

    for (int c = 0; c < NCHK; ++c){
        const size_t base = (size_t)bh*Lq + (size_t)c*32;
        const float* qg = q + base*256;
        const float* kg = k + base*256;
        const float* wg = w + base*256;
        const float* ug = u + base*256 + d0;
        const float* ag = attn + ((size_t)bh*NCHK + c)*1024;
        float*       og = o + base*256 + d0;

        for (int idx = tid; idx < 256*32; idx += 256){
            int r = idx >> 5, cc = idx & 31;
            float s = S[r*SLD + cc];
            float hi = __uint_as_float(__float_as_uint(s) & 0xFFFFE000u);
            Shi[r*SLD + cc] = hi;
            Slo[r*SLD + cc] = wmma::__float_to_tf32(s - hi);
        }
        __syncthreads();

        if (warp < 4){
            const int i0 = (warp & 1)*16, j0 = (warp >> 1)*16;
            wmma::fragment<wmma::accumulator,16,16,8,float> acc;
            wmma::load_matrix_sync(acc, ug + (size_t)i0*256 + j0, 256, wmma::mem_row_major);
            #pragma unroll 4
            for (int dk0 = 0; dk0 < 256; dk0 += 8){
                wmma::fragment<wmma::matrix_a,16,16,8,wmma::precision::tf32,wmma::row_major> af;
                wmma::load_matrix_sync(af, wg + (size_t)i0*256 + dk0, 256);
                #pragma unroll
                for (int t=0;t<af.num_elements;t++) af.x[t] = wmma::__float_to_tf32(-af.x[t]);
                wmma::fragment<wmma::matrix_b,16,16,8,wmma::precision::tf32,wmma::row_major> bf;
                wmma::load_matrix_sync(bf, Shi + dk0*SLD + j0, SLD);
                wmma::mma_sync(acc, af, bf, acc);
                wmma::load_matrix_sync(bf, Slo + dk0*SLD + j0, SLD);
                wmma::mma_sync(acc, af, bf, acc);
            }
            wmma::store_matrix_sync(uh + i0*SLD + j0, acc, SLD, wmma::mem_row_major);
        } else {
            const int i0 = ((warp-4) & 1)*16, j0 = ((warp-4) >> 1)*16;
            wmma::fill_fragment(acc2, 0.f);
            #pragma unroll 4
            for (int dk0 = 0; dk0 < 256; dk0 += 8){
                wmma::fragment<wmma::matrix_a,16,16,8,wmma::precision::tf32,wmma::row_major> af;
                wmma::load_matrix_sync(af, qg + (size_t)i0*256 + dk0, 256);
                #pragma unroll
                for (int t=0;t<af.num_elements;t++) af.x[t] = wmma::__float_to_tf32(af.x[t]);
                wmma::fragment<wmma::matrix_b,16,16,8,wmma::precision::tf32,wmma::row_major> bf;
                wmma::load_matrix_sync(bf, Shi + dk0*SLD + j0, SLD);
                wmma::mma_sync(acc2, af, bf, acc2);
                wmma::load_matrix_sync(bf, Slo + dk0*SLD + j0, SLD);
                wmma::mma_sync(acc2, af, bf, acc2);
            }
        }
        __syncthreads();

        for (int idx = tid; idx < 1024; idx += 256){
            int r = idx >> 5, cc = idx & 31;
            float s = uh[r*SLD + cc];
            float hi = __uint_as_float(__float_as_uint(s) & 0xFFFFE000u);
            uhh[r*SLD + cc] = hi;
            uhl[r*SLD + cc] = wmma::__float_to_tf32(s - hi);
        }
        __syncthreads();

        if (warp < 4){
            #pragma unroll
            for (int t = 0; t < 8; t++){
                const int id = warp*8 + t;
                const int dk0 = (id >> 1)*16, j0 = (id & 1)*16;
                wmma::fragment<wmma::accumulator,16,16,8,float> acc;
                wmma::load_matrix_sync(acc, S + dk0*SLD + j0, SLD, wmma::mem_row_major);
                #pragma unroll
                for (int i2 = 0; i2 < 32; i2 += 8){
                    wmma::fragment<wmma::matrix_a,16,16,8,wmma::precision::tf32,wmma::col_major> af;
                    wmma::load_matrix_sync(af, kg + (size_t)i2*256 + dk0, 256);
                    #pragma unroll
                    for (int tt=0;tt<af.num_elements;tt++) af.x[tt] = wmma::__float_to_tf32(af.x[tt]);
                    wmma::fragment<wmma::matrix_b,16,16,8,wmma::precision::tf32,wmma::row_major> bf;
                    wmma::load_matrix_sync(bf, uhh + i2*SLD + j0, SLD);
                    wmma::mma_sync(acc, af, bf, acc);
                    wmma::load_matrix_sync(bf, uhl + i2*SLD + j0, SLD);
                    wmma::mma_sync(acc, af, bf, acc);
                }
                wmma::store_matrix_sync(S + dk0*SLD + j0, acc, SLD, wmma::mem_row_major);
            }
        } else {
            const int i0 = ((warp-4) & 1)*16, j0 = ((warp-4) >> 1)*16;
            #pragma unroll
            for (int i2 = 0; i2 < 32; i2 += 8){
                wmma::fragment<wmma::matrix_a,16,16,8,wmma::precision::tf32,wmma::row_major> af;
                wmma::load_matrix_sync(af, ag + i0*32 + i2, 32);
                #pragma unroll
                for (int tt=0;tt<af.num_elements;tt++) af.x[tt] = wmma::__float_to_tf32(af.x[tt]);
                wmma::fragment<wmma::matrix_b,16,16,8,wmma::precision::tf32,wmma::row_major> bf;
                wmma::load_matrix_sync(bf, uhh + i2*SLD + j0, SLD);
                wmma::mma_sync(acc2, af, bf, acc2);
                wmma::load_matrix_sync(bf, uhl + i2*SLD + j0, SLD);
                wmma::mma_sync(acc2, af, bf, acc2);
            }
            wmma::store_matrix_sync(og + (size_t)i0*256 + j0, acc2, 256, wmma::mem_row_major);
        }
        __syncthreads();
    }
}

// ---------------- dual EMA (128 blocks x 32 threads) ----------------
__global__ void ema_kernel(const float* __restrict__ v, const float* __restrict__ gs,
                           const float* __restrict__ gl,
                           float* __restrict__ es, float* __restrict__ el)
{
    const int bh = blockIdx.x >> 3;
    const int dv = ((blockIdx.x & 7) << 5) + threadIdx.x;
    const size_t vbase = (size_t)bh*Lq*256 + dv;
    const float* gsp = gs + (size_t)bh*Lq;
    const float* glp = gl + (size_t)bh*Lq;
    float ss = 0.f, sl = 0.f;
    #pragma unroll 8
    for (int t=0;t<Lq;t++){
        float vv = v[vbase + (size_t)t*256];
        float a = gsp[t], b2 = glp[t];
        ss = fmaf(a, ss, (1.f-a)*vv);
        sl = fmaf(b2, sl, (1.f-b2)*vv);
        es[vbase + (size_t)t*256] = ss;
        el[vbase + (size_t)t*256] = sl;
    }
}

// ---------------- hierarchical gate heads ----------------
__global__ void gate_head_kernel(const float* __restrict__ z,
                                 const float* __restrict__ Wc, const float* __restrict__ bc,
                                 const float* __restrict__ Wl, const float* __restrict__ bl,
                                 const float* __restrict__ Wg, const float* __restrict__ bg,
                                 const float* __restrict__ ltc, const float* __restrict__ ltf,
                                 float* __restrict__ wgt)
{
    const int row = blockIdx.x;
    const float* zr = z + (size_t)row*512;
    float acc[24];
    #pragma unroll
    for (int r=0;r<24;r++) acc[r]=0.f;
    for (int j=threadIdx.x;j<512;j+=256){
        float zv = zr[j];
        #pragma unroll
        for (int r=0;r<8;r++){
            acc[r]    = fmaf(zv, Wc[r*512+j], acc[r]);
            acc[8+r]  = fmaf(zv, Wl[r*512+j], acc[8+r]);
            acc[16+r] = fmaf(zv, Wg[r*512+j], acc[16+r]);
        }
    }
    __shared__ float red[24][9];
    const int lane = threadIdx.x&31, w = threadIdx.x>>5;
    #pragma unroll
    for (int r=0;r<24;r++){
        float s = warp_sum(acc[r]);
        if (lane==0) red[r][w] = s;
    }
    __syncthreads();
    if (threadIdx.x < 4){
        const int h = threadIdx.x;
        float sums[6];
        int rs[6] = {2*h, 2*h+1, 8+2*h, 8+2*h+1, 16+2*h, 16+2*h+1};
        #pragma unroll
        for (int t=0;t<6;t++){
            float s=0.f;
            #pragma unroll
            for (int ww=0;ww<8;ww++) s += red[rs[t]][ww];
            sums[t]=s;
        }
        float tc = log1pf(expf(ltc[h])) + 1e-4f;
        float tf = log1pf(expf(ltf[h])) + 1e-4f;
        float c0 = sums[0]+bc[2*h], c1 = sums[1]+bc[2*h+1];
        float l0 = sums[2]+bl[2*h], l1 = sums[3]+bl[2*h+1];
        float g0 = sums[4]+bg[2*h], g1 = sums[5]+bg[2*h+1];
        float pg0 = sigm((c0-c1)/tc), pg1 = 1.f - pg0;
        float q0  = sigm((l0-l1)/tf), q1 = 1.f - q0;
        float r0  = sigm((g0-g1)/tf), r1 = 1.f - r0;
        size_t o = (size_t)row*16 + h*4;
        wgt[o+0] = pg0*q0; wgt[o+1] = pg0*q1; wgt[o+2] = pg1*r0; wgt[o+3] = pg1*r1;
    }
}

// ---------------- mix + per-head RMSNorm ----------------
__global__ void combine_kernel(const float* __restrict__ v, const float* __restrict__ es,
                               const float* __restrict__ el, const float* __restrict__ dl,
                               const float* __restrict__ wgt, const float* __restrict__ onw,
                               float* __restrict__ omix)
{
    const int blk = blockIdx.x;           // row*4 + h
    const int row = blk >> 2, h = blk & 3;
    const int b = row >> 12, l = row & (Lq-1);
    const int tid = threadIdx.x;
    const size_t gbase = ((size_t)(b*4+h)*Lq + l)*256 + tid;
    const float* wp = wgt + (size_t)row*16 + h*4;
    float w0 = wp[0], w1 = wp[1], w2 = wp[2], w3 = wp[3];
    float val = w0*v[gbase] + w1*es[gbase] + w2*dl[gbase] + w3*el[gbase];

    float s = warp_sum(val*val);
    __shared__ float red[8];
    const int lane = tid&31, w = tid>>5;
    if (lane==0) red[w] = s;
    __syncthreads();
    if (w==0){
        float t = (lane<8)?red[lane]:0.f;
        t = warp_sum(t);
        if (lane==0) red[0] = t;
    }
    __syncthreads();
    float rms = rsqrtf(red[0]*(1.f/256.f) + 1e-5f);
    omix[(size_t)row*1024 + h*256 + tid] = val*rms*onw[tid];
}

// ---------------- host ----------------
extern "C" void kernel_launch(void* const* d_in, const int* in_sizes, int n_in,
                              void* d_out, int out_size)
{
    const float* x      = (const float*)d_in[0];
    const float* Wq     = (const float*)d_in[1];
    const float* Wk     = (const float*)d_in[2];
    const float* Wv     = (const float*)d_in[3];
    const float* cqw    = (const float*)d_in[4];
    const float* ckw    = (const float*)d_in[5];
    const float* cvw    = (const float*)d_in[6];
    const float* Wb     = (const float*)d_in[7];
    const float* Wds    = (const float*)d_in[8];
    const float* bds    = (const float*)d_in[9];
    const float* Wdl    = (const float*)d_in[10];
    const float* bdl    = (const float*)d_in[11];
    const float* Wtrunk = (const float*)d_in[12];
    const float* btrunk = (const float*)d_in[13];
    const float* Wcoarse= (const float*)d_in[14];
    const float* bcoarse= (const float*)d_in[15];
    const float* Wlocal = (const float*)d_in[16];
    const float* blocal = (const float*)d_in[17];
    const float* Wglobal= (const float*)d_in[18];
    const float* bglobal= (const float*)d_in[19];
    const float* ltc    = (const float*)d_in[20];
    const float* ltf    = (const float*)d_in[21];
    const float* onw    = (const float*)d_in[22];
    const float* Wo     = (const float*)d_in[23];
    float* out = (float*)d_out;

    float* arena;
    cudaGetSymbolAddress((void**)&arena, g_arena);
    float* qpre = arena + OFF_QPRE;
    float* kpre = arena + OFF_KPRE;
    float* vpre = arena + OFF_VPRE;
    float* qb   = arena + OFF_Q;
    float* kb   = arena + OFF_K;
    float* vb   = arena + OFF_V;
    float* ub   = arena + OFF_U;
    float* wb   = arena + OFF_W;
    float* dlt  = arena + OFF_DELTA;
    float* emas = arena + OFF_EMAS;
    float* emal = arena + OFF_EMAL;
    float* omix = arena + OFF_OMIX;
    float* zb   = arena + OFF_Z;
    float* attn = arena + OFF_ATTN;
    float* beta = arena + OFF_BETA;
    float* gs   = arena + OFF_GS;
    float* gl   = arena + OFF_GL;
    float* wgt  = arena + OFF_WGT;

    cudaFuncSetAttribute(gemm_tf32_kernel, cudaFuncAttributeMaxDynamicSharedMemorySize, GEMM_SMEM_BYTES);
    cudaFuncSetAttribute(chunk_pre_kernel, cudaFuncAttributeMaxDynamicSharedMemorySize, PRE_SMEM_BYTES);
    cudaFuncSetAttribute(scan_kernel,      cudaFuncAttributeMaxDynamicSharedMemorySize, SCAN_SMEM_BYTES);

    dim3 blk(256);
    dim3 gN(1024/GBN, MROWS/GBM);
    dim3 gZ(512/GBN,  MROWS/GBM);

    // projections (TF32 tensor cores, 3-stage pipeline)
    gemm_tf32_kernel<<<gN, blk, GEMM_SMEM_BYTES>>>(x, Wq, nullptr, qpre, MROWS, 1024, 1024, 0);
    gemm_tf32_kernel<<<gN, blk, GEMM_SMEM_BYTES>>>(x, Wk, nullptr, kpre, MROWS, 1024, 1024, 0);
    gemm_tf32_kernel<<<gN, blk, GEMM_SMEM_BYTES>>>(x, Wv, nullptr, vpre, MROWS, 1024, 1024, 0);

    // conv + silu + relayout
    conv_silu_kernel<<<dim3(MROWS,4), blk>>>(qpre, kpre, vpre, cqw, ckw, cvw, qb, kb, vb);

    // beta / decays
    smallproj_kernel<<<MROWS, blk>>>(x, Wb, Wds, bds, Wdl, bdl, beta, gs, gl);

    // delta rule
    chunk_pre_kernel<<<2048, blk, PRE_SMEM_BYTES>>>(qb, kb, vb, beta, ub, wb, attn);
    scan_kernel<<<128, blk, SCAN_SMEM_BYTES>>>(qb, kb, ub, wb, attn, dlt);

    // EMAs
    ema_kernel<<<128, 32>>>(vb, gs, gl, emas, emal);

    // gate
    gemm_tf32_kernel<<<gZ, blk, GEMM_SMEM_BYTES>>>(x, Wtrunk, btrunk, zb, MROWS, 512, 1024, 1);
    gate_head_kernel<<<MROWS, blk>>>(zb, Wcoarse, bcoarse, Wlocal, blocal,
                                     Wglobal, bglobal, ltc, ltf, wgt);

    // combine + RMSNorm
    combine_kernel<<<MROWS*4, blk>>>(vb, emas, emal, dlt, wgt, onw, omix);

    // output projection
    gemm_tf32_kernel<<<gN, blk, GEMM_SMEM_BYTES>>>(omix, Wo, nullptr, out, MROWS, 1024, 1024, 0);
}

// round 7
// speedup vs baseline: 1.0847x; 1.0847x over previous
#include <cuda_runtime.h>
#include <math.h>
#include <mma.h>

using namespace nvcuda;

#define Hq   4
#define Lq   4096
#define Dq   1024
#define CHK  32
#define NCHK 128
#define MROWS 16384

// ---------------- scratch arena (no cudaMalloc allowed) ----------------
constexpr size_t SZf      = 16777216ull;            // 16384*1024
constexpr size_t OFF_QPRE = 0;                      // reused later as U
constexpr size_t OFF_U    = 0;
constexpr size_t OFF_KPRE = SZf;                    // reused later as W
constexpr size_t OFF_W    = SZf;
constexpr size_t OFF_VPRE = 2*SZf;                  // reused later as DELTA_O
constexpr size_t OFF_DELTA= 2*SZf;
constexpr size_t OFF_Q    = 3*SZf;
constexpr size_t OFF_K    = 4*SZf;
constexpr size_t OFF_V    = 5*SZf;
constexpr size_t OFF_EMAS = 6*SZf;
constexpr size_t OFF_EMAL = 7*SZf;
constexpr size_t OFF_OMIX = 8*SZf;
constexpr size_t OFF_Z    = 9*SZf;                  // 16384*512
constexpr size_t OFF_ATTN = OFF_Z + 8388608ull;     // 2048*1024
constexpr size_t OFF_BETA = OFF_ATTN + 2097152ull;  // 65536
constexpr size_t OFF_GS   = OFF_BETA + 65536ull;
constexpr size_t OFF_GL   = OFF_GS + 65536ull;
constexpr size_t OFF_WGT  = OFF_GL + 65536ull;      // 16384*16
constexpr size_t ARENA_TOTAL = OFF_WGT + 262144ull;

__device__ float g_arena[ARENA_TOTAL];

constexpr int PRE_SMEM_BYTES  = 26816 * 4;   // 107264

// wmma scan smem: S, Shi, Slo (256x36) + uh, uhh, uhl (32x36)
constexpr int SLD = 36;
constexpr int SCAN_SMEM_FLOATS = 3*256*SLD + 3*32*SLD;  // 31104
constexpr int SCAN_SMEM_BYTES  = SCAN_SMEM_FLOATS * 4;  // 124416

// GEMM tiling (R4 proven config): 128x64 tile, BK=32, 2-stage
constexpr int GBM = 128, GBN = 64, GBK = 32, GAP = 36;
constexpr int GSTAGE = (GBM+GBN)*GAP;            // 6912 floats per stage
constexpr int GEMM_SMEM_BYTES = 2*GSTAGE*4;      // 55296

__device__ __forceinline__ float sigm(float x){ return 1.f/(1.f+expf(-x)); }
__device__ __forceinline__ float silu(float x){ return x/(1.f+expf(-x)); }

__device__ __forceinline__ float warp_sum(float v){
    #pragma unroll
    for (int o=16;o>0;o>>=1) v += __shfl_xor_sync(0xffffffffu, v, o);
    return v;
}

__device__ __forceinline__ void cp16(float* s, const float* g){
    unsigned a = (unsigned)__cvta_generic_to_shared(s);
    asm volatile("cp.async.cg.shared.global [%0], [%1], 16;" :: "r"(a), "l"(g));
}

// ---------------- GEMM core (device inline): C[M,N]=A@W^T, 128x64 tile ------
__device__ __forceinline__ void gemm_body(const float* __restrict__ A, const float* __restrict__ W,
                                          const float* __restrict__ bias, float* __restrict__ C,
                                          int N, int K, int act, int m0, int n0, float* smem)
{
    const int tid = threadIdx.x, warp = tid>>5;
    const int tr = warp>>1, tcw = warp&1;
    const int lr = tid>>3, lc = (tid&7)*4;

    wmma::fragment<wmma::accumulator,16,16,8,float> acc[2][2];
    #pragma unroll
    for(int i=0;i<2;i++)
        #pragma unroll
        for(int j=0;j<2;j++) wmma::fill_fragment(acc[i][j], 0.f);

    const int KT = K/GBK;

    {
        float* As = smem;
        float* Ws = As + GBM*GAP;
        #pragma unroll
        for (int s=0;s<4;s++){
            int r = lr + s*32;
            cp16(&As[r*GAP+lc], &A[(size_t)(m0+r)*K + lc]);
        }
        #pragma unroll
        for (int s=0;s<2;s++){
            int r = lr + s*32;
            cp16(&Ws[r*GAP+lc], &W[(size_t)(n0+r)*K + lc]);
        }
        asm volatile("cp.async.commit_group;");
    }

    int buf = 0;
    for (int it=0; it<KT; ++it){
        if (it+1 < KT){
            float* As = smem + (buf^1)*GSTAGE;
            float* Ws = As + GBM*GAP;
            const int k0 = (it+1)*GBK;
            #pragma unroll
            for (int s=0;s<4;s++){
                int r = lr + s*32;
                cp16(&As[r*GAP+lc], &A[(size_t)(m0+r)*K + k0 + lc]);
            }
            #pragma unroll
            for (int s=0;s<2;s++){
                int r = lr + s*32;
                cp16(&Ws[r*GAP+lc], &W[(size_t)(n0+r)*K + k0 + lc]);
            }
            asm volatile("cp.async.commit_group;");
            asm volatile("cp.async.wait_group 1;");
        } else {
            asm volatile("cp.async.wait_group 0;");
        }
        __syncthreads();

        float* As = smem + buf*GSTAGE;
        float* Ws = As + GBM*GAP;
        #pragma unroll
        for (int kk=0; kk<GBK; kk+=8){
            wmma::fragment<wmma::matrix_a,16,16,8,wmma::precision::tf32,wmma::row_major> af[2];
            wmma::fragment<wmma::matrix_b,16,16,8,wmma::precision::tf32,wmma::col_major> bf[2];
            #pragma unroll
            for (int i=0;i<2;i++){
                wmma::load_matrix_sync(af[i], &As[(tr*32+i*16)*GAP + kk], GAP);
                #pragma unroll
                for (int t=0;t<af[i].num_elements;t++) af[i].x[t] = wmma::__float_to_tf32(af[i].x[t]);
            }
            #pragma unroll
            for (int j=0;j<2;j++){
                wmma::load_matrix_sync(bf[j], &Ws[(tcw*32+j*16)*GAP + kk], GAP);
                #pragma unroll
                for (int t=0;t<bf[j].num_elements;t++) bf[j].x[t] = wmma::__float_to_tf32(bf[j].x[t]);
            }
            #pragma unroll
            for (int i=0;i<2;i++)
                #pragma unroll
                for (int j=0;j<2;j++)
                    wmma::mma_sync(acc[i][j], af[i], bf[j], acc[i][j]);
        }
        __syncthreads();
        buf ^= 1;
    }

    float* Cs = smem;   // [128][72]
    #pragma unroll
    for (int i=0;i<2;i++)
        #pragma unroll
        for (int j=0;j<2;j++)
            wmma::store_matrix_sync(&Cs[(tr*32+i*16)*72 + tcw*32 + j*16], acc[i][j], 72, wmma::mem_row_major);
    __syncthreads();

    for (int idx = tid; idx < GBM*GBN/4; idx += 256){
        int row = idx >> 4, col = (idx & 15)*4;
        float4 v4 = *reinterpret_cast<float4*>(&Cs[row*72 + col]);
        float* vv = (float*)&v4;
        #pragma unroll
        for (int j=0;j<4;j++){
            float v = vv[j];
            if (bias) v += bias[n0+col+j];
            if (act==1) v = v/(1.f+expf(-v));
            vv[j] = v;
        }
        *reinterpret_cast<float4*>(&C[(size_t)(m0+row)*N + n0+col]) = v4;
    }
}

// ---------------- mega GEMM: Q | K | V | trunk fused in one launch ----------
// gridDim.x = 16 + 16 + 16 + 8 = 56, gridDim.y = 128
__global__ void megagemm_kernel(const float* __restrict__ x,
                                const float* __restrict__ Wq, const float* __restrict__ Wk,
                                const float* __restrict__ Wv, const float* __restrict__ Wt,
                                const float* __restrict__ bt,
                                float* __restrict__ qpre, float* __restrict__ kpre,
                                float* __restrict__ vpre, float* __restrict__ zb)
{
    extern __shared__ float smem[];
    const int bx = blockIdx.x;
    const int m0 = blockIdx.y*GBM;
    const float* W; float* C; const float* bias = nullptr;
    int N, act = 0, nb;
    if (bx < 16)      { W = Wq; C = qpre; N = 1024; nb = bx; }
    else if (bx < 32) { W = Wk; C = kpre; N = 1024; nb = bx-16; }
    else if (bx < 48) { W = Wv; C = vpre; N = 1024; nb = bx-32; }
    else              { W = Wt; C = zb;   N = 512;  nb = bx-48; bias = bt; act = 1; }
    gemm_body(x, W, bias, C, N, 1024, act, m0, nb*GBN, smem);
}

// ---------------- standalone GEMM (output projection) ----------------
__global__ void gemm_tf32_kernel(const float* __restrict__ A, const float* __restrict__ W,
                                 float* __restrict__ C, int N, int K)
{
    extern __shared__ float smem[];
    gemm_body(A, W, nullptr, C, N, K, 0, blockIdx.y*GBM, blockIdx.x*GBN, smem);
}

// ---------------- causal depthwise conv (k=4) + SiLU, float4, relayout ------
__global__ void conv_silu_kernel(const float* __restrict__ qp, const float* __restrict__ kp,
                                 const float* __restrict__ vp,
                                 const float* __restrict__ wq, const float* __restrict__ wk,
                                 const float* __restrict__ wv,
                                 float* __restrict__ qo, float* __restrict__ ko,
                                 float* __restrict__ vo)
{
    const int row = blockIdx.x;                 // b*L + l
    const int d4  = threadIdx.x * 4;            // 0..1020
    const int l = row & (Lq-1), b = row >> 12;

    // per-channel taps (4 channels x 4 taps)
    float4 wq_c[4], wk_c[4], wv_c[4];
    #pragma unroll
    for (int c=0;c<4;c++){
        wq_c[c] = *reinterpret_cast<const float4*>(wq + (d4+c)*4);
        wk_c[c] = *reinterpret_cast<const float4*>(wk + (d4+c)*4);
        wv_c[c] = *reinterpret_cast<const float4*>(wv + (d4+c)*4);
    }

    float aq[4] = {0,0,0,0}, ak[4] = {0,0,0,0}, av[4] = {0,0,0,0};
    #pragma unroll
    for (int j=0;j<4;j++){
        if (l - 3 + j >= 0){
            size_t idx = (size_t)(row - 3 + j)*Dq + d4;
            float4 xq = *reinterpret_cast<const float4*>(qp + idx);
            float4 xk = *reinterpret_cast<const float4*>(kp + idx);
            float4 xv = *reinterpret_cast<const float4*>(vp + idx);
            const float* xqf = (const float*)&xq;
            const float* xkf = (const float*)&xk;
            const float* xvf = (const float*)&xv;
            #pragma unroll
            for (int c=0;c<4;c++){
                aq[c] = fmaf(xqf[c], ((const float*)&wq_c[c])[j], aq[c]);
                ak[c] = fmaf(xkf[c], ((const float*)&wk_c[c])[j], ak[c]);
                av[c] = fmaf(xvf[c], ((const float*)&wv_c[c])[j], av[c]);
            }
        }
    }
    const int h = d4 >> 8, dk = d4 & 255;
    size_t o = ((size_t)(b*Hq + h)*Lq + l)*256 + dk;
    float4 oq, ok, ov;
    float* oqf = (float*)&oq; float* okf = (float*)&ok; float* ovf = (float*)&ov;
    #pragma unroll
    for (int c=0;c<4;c++){
        oqf[c] = silu(aq[c]);
        okf[c] = silu(ak[c]);
        ovf[c] = silu(av[c]);
    }
    *reinterpret_cast<float4*>(qo + o) = oq;
    *reinterpret_cast<float4*>(ko + o) = ok;
    *reinterpret_cast<float4*>(vo + o) = ov;
}

// ---------------- beta / g_s / g_l projections ----------------
__global__ void smallproj_kernel(const float* __restrict__ x,
                                 const float* __restrict__ Wb, const float* __restrict__ Wds,
                                 const float* __restrict__ bds, const float* __restrict__ Wdl,
                                 const float* __restrict__ bdl,
                                 float* __restrict__ beta, float* __restrict__ gs,
                                 float* __restrict__ gl)
{
    const int row = blockIdx.x;
    const float* xr = x + (size_t)row*Dq;
    float acc[12];
    #pragma unroll
    for (int r=0;r<12;r++) acc[r]=0.f;
    for (int j=threadIdx.x;j<Dq;j+=256){
        const float xv = xr[j];
        #pragma unroll
        for (int h=0;h<4;h++){
            acc[h]   = fmaf(xv, Wb [h*Dq+j], acc[h]);
            acc[4+h] = fmaf(xv, Wds[h*Dq+j], acc[4+h]);
            acc[8+h] = fmaf(xv, Wdl[h*Dq+j], acc[8+h]);
        }
    }
    __shared__ float red[12][9];
    const int lane = threadIdx.x & 31, w = threadIdx.x >> 5;
    #pragma unroll
    for (int r=0;r<12;r++){
        float s = warp_sum(acc[r]);
        if (lane==0) red[r][w] = s;
    }
    __syncthreads();
    if (threadIdx.x < 12){
        float s = 0.f;
        #pragma unroll
        for (int ww=0;ww<8;ww++) s += red[threadIdx.x][ww];
        const int h = threadIdx.x & 3;
        const int b = row >> 12, l = row & (Lq-1);
        size_t o = (size_t)(b*4 + h)*Lq + l;
        if (threadIdx.x < 4)      beta[o] = sigm(s);
        else if (threadIdx.x < 8) gs[o]   = sigm(s + bds[h]);
        else                      gl[o]   = sigm(s + bdl[h]);
    }
}

// ---------------- delta-rule per-chunk precompute ----------------
__global__ void chunk_pre_kernel(float* __restrict__ q, float* __restrict__ k,
                                 const float* __restrict__ v, const float* __restrict__ beta,
                                 float* __restrict__ u, float* __restrict__ w,
                                 float* __restrict__ attn)
{
    extern __shared__ float sm[];
    float* qs = sm;              // 32*257
    float* ks = qs + 8224;
    float* vs = ks + 8224;
    float* Lm = vs + 8224;       // 32*33
    float* Ti = Lm + 1056;       // 32*33
    float* bs = Ti + 1056;       // 32
    const int bh = blockIdx.x >> 7;
    const int c  = blockIdx.x & 127;
    const int tid = threadIdx.x, lane = tid&31, wid = tid>>5;
    const size_t base = (size_t)bh*Lq + (size_t)c*CHK;

    for (int idx = tid; idx < 32*256; idx += 256){
        int i = idx >> 8, d = idx & 255;
        size_t g = (base + i)*256 + d;
        qs[i*257+d] = q[g];
        ks[i*257+d] = k[g];
        vs[i*257+d] = v[g];
    }
    if (tid < 32) bs[tid] = beta[base + tid];
    __syncthreads();

    #pragma unroll
    for (int r=0;r<4;r++){
        int i = wid*4 + r;
        float sq=0.f, sk=0.f;
        for (int d=lane; d<256; d+=32){
            float a=qs[i*257+d]; sq=fmaf(a,a,sq);
            float bb=ks[i*257+d]; sk=fmaf(bb,bb,sk);
        }
        sq = warp_sum(sq); sk = warp_sum(sk);
        float rq = rsqrtf(sq + 1e-6f), rk = rsqrtf(sk + 1e-6f);
        for (int d=lane; d<256; d+=32){ qs[i*257+d]*=rq; ks[i*257+d]*=rk; }
    }
    __syncthreads();

    for (int idx = tid; idx < 32*256; idx += 256){
        int i = idx>>8, d = idx&255;
        size_t g = (base+i)*256 + d;
        q[g] = qs[i*257+d];
        k[g] = ks[i*257+d];
        vs[i*257+d] *= bs[i];
    }
    __syncthreads();

    #pragma unroll
    for (int r=0;r<4;r++){
        int i = wid + 8*r;
        float aq=0.f, akk=0.f;
        for (int d=0; d<256; d++){
            float kjd = ks[lane*257+d];
            aq  = fmaf(qs[i*257+d], kjd, aq);
            akk = fmaf(ks[i*257+d], kjd, akk);
        }
        Lm[i*33+lane] = (lane < i) ? bs[i]*akk : 0.f;
        attn[(size_t)blockIdx.x*1024 + i*32 + lane] = (lane <= i) ? aq : 0.f;
    }
    __syncthreads();

    if (wid == 0){
        for (int i=0;i<32;i++){
            float xv = (lane==i) ? 1.f : 0.f;
            for (int p=0;p<i;p++) xv = fmaf(-Lm[i*33+p], Ti[p*33+lane], xv);
            Ti[i*33+lane] = xv;
            __syncwarp();
        }
    }
    __syncthreads();

    for (int idx = tid; idx < 1024; idx += 256){
        int i = idx>>5, j = idx&31;
        Lm[i*33+j] = Ti[i*33+j]*bs[j];
    }
    __syncthreads();

    #pragma unroll
    for (int r=0;r<4;r++){
        int i = wid + 8*r;
        #pragma unroll
        for (int m=0;m<8;m++){
            int d = lane + 32*m;
            float au=0.f, aw=0.f;
            #pragma unroll
            for (int j=0;j<32;j++){
                au = fmaf(Ti[i*33+j], vs[j*257+d], au);
                aw = fmaf(Lm[i*33+j], ks[j*257+d], aw);
            }
            size_t g = (base+i)*256 + d;
            u[g] = au;
            w[g] = aw;
        }
    }
}

// ---------------- fused: delta-scan (blocks 0-127) + dual EMA (blocks 128-143) ----
__global__ void scan_ema_kernel(const float* __restrict__ q, const float* __restrict__ k,
                                const float* __restrict__ u, const float* __restrict__ w,
                                const float* __restrict__ attn, float* __restrict__ o,
                                const float* __restrict__ v, const float* __restrict__ gs,
                                const float* __restrict__ gl,
                                float* __restrict__ es, float* __restrict__ el)
{
    if (blockIdx.x >= 128){
        // ---- EMA part: 16 blocks x 256 threads ----
        const int bh = blockIdx.x - 128;
        const int dv = threadIdx.x;
        const size_t vbase = (size_t)bh*Lq*256 + dv;
        const float* gsp = gs + (size_t)bh*Lq;
        const float* glp = gl + (size_t)bh*Lq;
        float ss = 0.f, sl = 0.f;
        #pragma unroll 8
        for (int t=0;t<Lq;t++){
            float vv = v[vbase + (size_t)t*256];
            float a = gsp[t], b2 = glp[t];
            ss = fmaf(a, ss, (1.f-a)*vv);
            sl = fmaf(b2, sl, (1.f-b2)*vv);
            es[vbase + (size_t)t*256] = ss;
            el[vbase + (size_t)t*256] = sl;
        }
        return;
    }

    extern __shared__ float sm[];
    float* S   = sm;                  // 256*36 fp32 master
    float* Shi = S   + 256*SLD;
    float* Slo = Shi + 256*SLD;
    float* uh  = Slo + 256*SLD;       // 32*36
    float* uhh = uh  + 32*SLD;
    float* uhl = uhh + 32*SLD;
    const int bh = blockIdx.x >> 3;
    const int d0 = (blockIdx.x & 7) * 32;
    const int tid = threadIdx.x, warp = tid >> 5;

    for (int i = tid; i < 3*256*SLD; i += 256) sm[i] = 0.f;
    __syncthreads();

    wmma::fragment<wmma::accumulator,16,16,8,float> acc2;

    for (int c = 0; c < NCHK; ++c){
        const size_t base = (size_t)bh*Lq + (size_t)c*32;
        const float* qg = q + base*256;
        const float* kg = k + base*256;
        const float* wg = w + base*256;
        const float* ug = u + base*256 + d0;
        const float* ag = attn + ((size_t)bh*NCHK + c)*1024;
        float*       og = o + base*256 + d0;

        for (int idx = tid; idx < 256*32; idx += 256){
            int r = idx >> 5, cc = idx & 31;
            float s = S[r*SLD + cc];
            float hi = __uint_as_float(__float_as_uint(s) & 0xFFFFE000u);
            Shi[r*SLD + cc] = hi;
            Slo[r*SLD + cc] = wmma::__float_to_tf32(s - hi);
        }
        __syncthreads();

        if (warp < 4){
            const int i0 = (warp & 1)*16, j0 = (warp >> 1)*16;
            wmma::fragment<wmma::accumulator,16,16,8,float> acc;
            wmma::load_matrix_sync(acc, ug + (size_t)i0*256 + j0, 256, wmma::mem_row_major);
            #pragma unroll 4
            for (int dk0 = 0; dk0 < 256; dk0 += 8){
                wmma::fragment<wmma::matrix_a,16,16,8,wmma::precision::tf32,wmma::row_major> af;
                wmma::load_matrix_sync(af, wg + (size_t)i0*256 + dk0, 256);
                #pragma unroll
                for (int t=0;t<af.num_elements;t++) af.x[t] = wmma::__float_to_tf32(-af.x[t]);
                wmma::fragment<wmma::matrix_b,16,16,8,wmma::precision::tf32,wmma::row_major> bf;
                wmma::load_matrix_sync(bf, Shi + dk0*SLD + j0, SLD);
                wmma::mma_sync(acc, af, bf, acc);
                wmma::load_matrix_sync(bf, Slo + dk0*SLD + j0, SLD);
                wmma::mma_sync(acc, af, bf, acc);
            }
            wmma::store_matrix_sync(uh + i0*SLD + j0, acc, SLD, wmma::mem_row_major);
        } else {
            const int i0 = ((warp-4) & 1)*16, j0 = ((warp-4) >> 1)*16;
            wmma::fill_fragment(acc2, 0.f);
            #pragma unroll 4
            for (int dk0 = 0; dk0 < 256; dk0 += 8){
                wmma::fragment<wmma::matrix_a,16,16,8,wmma::precision::tf32,wmma::row_major> af;
                wmma::load_matrix_sync(af, qg + (size_t)i0*256 + dk0, 256);
                #pragma unroll
                for (int t=0;t<af.num_elements;t++) af.x[t] = wmma::__float_to_tf32(af.x[t]);
                wmma::fragment<wmma::matrix_b,16,16,8,wmma::precision::tf32,wmma::row_major> bf;
                wmma::load_matrix_sync(bf, Shi + dk0*SLD + j0, SLD);
                wmma::mma_sync(acc2, af, bf, acc2);
                wmma::load_matrix_sync(bf, Slo + dk0*SLD + j0, SLD);
                wmma::mma_sync(acc2, af, bf, acc2);
            }
        }
        __syncthreads();

        for (int idx = tid; idx < 1024; idx += 256){
            int r = idx >> 5, cc = idx & 31;
            float s = uh[r*SLD + cc];
            float hi = __uint_as_float(__float_as_uint(s) & 0xFFFFE000u);
            uhh[r*SLD + cc] = hi;
            uhl[r*SLD + cc] = wmma::__float_to_tf32(s - hi);
        }
        __syncthreads();

        if (warp < 4){
            #pragma unroll
            for (int t = 0; t < 8; t++){
                const int id = warp*8 + t;
                const int dk0 = (id >> 1)*16, j0 = (id & 1)*16;
                wmma::fragment<wmma::accumulator,16,16,8,float> acc;
                wmma::load_matrix_sync(acc, S + dk0*SLD + j0, SLD, wmma::mem_row_major);
                #pragma unroll
                for (int i2 = 0; i2 < 32; i2 += 8){
                    wmma::fragment<wmma::matrix_a,16,16,8,wmma::precision::tf32,wmma::col_major> af;
                    wmma::load_matrix_sync(af, kg + (size_t)i2*256 + dk0, 256);
                    #pragma unroll
                    for (int tt=0;tt<af.num_elements;tt++) af.x[tt] = wmma::__float_to_tf32(af.x[tt]);
                    wmma::fragment<wmma::matrix_b,16,16,8,wmma::precision::tf32,wmma::row_major> bf;
                    wmma::load_matrix_sync(bf, uhh + i2*SLD + j0, SLD);
                    wmma::mma_sync(acc, af, bf, acc);
                    wmma::load_matrix_sync(bf, uhl + i2*SLD + j0, SLD);
                    wmma::mma_sync(acc, af, bf, acc);
                }
                wmma::store_matrix_sync(S + dk0*SLD + j0, acc, SLD, wmma::mem_row_major);
            }
        } else {
            const int i0 = ((warp-4) & 1)*16, j0 = ((warp-4) >> 1)*16;
            #pragma unroll
            for (int i2 = 0; i2 < 32; i2 += 8){
                wmma::fragment<wmma::matrix_a,16,16,8,wmma::precision::tf32,wmma::row_major> af;
                wmma::load_matrix_sync(af, ag + i0*32 + i2, 32);
                #pragma unroll
                for (int tt=0;tt<af.num_elements;tt++) af.x[tt] = wmma::__float_to_tf32(af.x[tt]);
                wmma::fragment<wmma::matrix_b,16,16,8,wmma::precision::tf32,wmma::row_major> bf;
                wmma::load_matrix_sync(bf, uhh + i2*SLD + j0, SLD);
                wmma::mma_sync(acc2, af, bf, acc2);
                wmma::load_matrix_sync(bf, uhl + i2*SLD + j0, SLD);
                wmma::mma_sync(acc2, af, bf, acc2);
            }
            wmma::store_matrix_sync(og + (size_t)i0*256 + j0, acc2, 256, wmma::mem_row_major);
        }
        __syncthreads();
    }
}

// ---------------- hierarchical gate heads ----------------
__global__ void gate_head_kernel(const float* __restrict__ z,
                                 const float* __restrict__ Wc, const float* __restrict__ bc,
                                 const float* __restrict__ Wl, const float* __restrict__ bl,
                                 const float* __restrict__ Wg, const float* __restrict__ bg,
                                 const float* __restrict__ ltc, const float* __restrict__ ltf,
                                 float* __restrict__ wgt)
{
    const int row = blockIdx.x;
    const float* zr = z + (size_t)row*512;
    float acc[24];
    #pragma unroll
    for (int r=0;r<24;r++) acc[r]=0.f;
    for (int j=threadIdx.x;j<512;j+=256){
        float zv = zr[j];
        #pragma unroll
        for (int r=0;r<8;r++){
            acc[r]    = fmaf(zv, Wc[r*512+j], acc[r]);
            acc[8+r]  = fmaf(zv, Wl[r*512+j], acc[8+r]);
            acc[16+r] = fmaf(zv, Wg[r*512+j], acc[16+r]);
        }
    }
    __shared__ float red[24][9];
    const int lane = threadIdx.x&31, w = threadIdx.x>>5;
    #pragma unroll
    for (int r=0;r<24;r++){
        float s = warp_sum(acc[r]);
        if (lane==0) red[r][w] = s;
    }
    __syncthreads();
    if (threadIdx.x < 4){
        const int h = threadIdx.x;
        float sums[6];
        int rs[6] = {2*h, 2*h+1, 8+2*h, 8+2*h+1, 16+2*h, 16+2*h+1};
        #pragma unroll
        for (int t=0;t<6;t++){
            float s=0.f;
            #pragma unroll
            for (int ww=0;ww<8;ww++) s += red[rs[t]][ww];
            sums[t]=s;
        }
        float tc = log1pf(expf(ltc[h])) + 1e-4f;
        float tf = log1pf(expf(ltf[h])) + 1e-4f;
        float c0 = sums[0]+bc[2*h], c1 = sums[1]+bc[2*h+1];
        float l0 = sums[2]+bl[2*h], l1 = sums[3]+bl[2*h+1];
        float g0 = sums[4]+bg[2*h], g1 = sums[5]+bg[2*h+1];
        float pg0 = sigm((c0-c1)/tc), pg1 = 1.f - pg0;
        float q0  = sigm((l0-l1)/tf), q1 = 1.f - q0;
        float r0  = sigm((g0-g1)/tf), r1 = 1.f - r0;
        size_t o = (size_t)row*16 + h*4;
        wgt[o+0] = pg0*q0; wgt[o+1] = pg0*q1; wgt[o+2] = pg1*r0; wgt[o+3] = pg1*r1;
    }
}

// ---------------- mix + per-head RMSNorm (warp per head-row, float4) --------
__global__ void combine_kernel(const float* __restrict__ v, const float* __restrict__ es,
                               const float* __restrict__ el, const float* __restrict__ dl,
                               const float* __restrict__ wgt, const float* __restrict__ onw,
                               float* __restrict__ omix)
{
    const int gw = blockIdx.x*8 + (threadIdx.x>>5);   // row*4 + h
    const int row = gw >> 2, h = gw & 3;
    const int b = row >> 12, l = row & (Lq-1);
    const int lane = threadIdx.x & 31;
    const size_t gbase = ((size_t)(b*4+h)*Lq + l)*256;
    const float* wp = wgt + (size_t)row*16 + h*4;
    const float w0 = wp[0], w1 = wp[1], w2 = wp[2], w3 = wp[3];

    float4 vals[2];
    float ss = 0.f;
    #pragma unroll
    for (int s=0;s<2;s++){
        const int d = lane*4 + s*128;
        float4 a = *reinterpret_cast<const float4*>(v  + gbase + d);
        float4 b4= *reinterpret_cast<const float4*>(es + gbase + d);
        float4 c4= *reinterpret_cast<const float4*>(dl + gbase + d);
        float4 d4= *reinterpret_cast<const float4*>(el + gbase + d);
        float* av=(float*)&a; float* bv=(float*)&b4; float* cv=(float*)&c4; float* dv=(float*)&d4;
        float* ov=(float*)&vals[s];
        #pragma unroll
        for (int j=0;j<4;j++){
            float val = w0*av[j] + w1*bv[j] + w2*cv[j] + w3*dv[j];
            ov[j] = val;
            ss = fmaf(val, val, ss);
        }
    }
    ss = warp_sum(ss);
    const float rms = rsqrtf(ss*(1.f/256.f) + 1e-5f);
    float* op = omix + (size_t)row*1024 + h*256;
    #pragma unroll
    for (int s=0;s<2;s++){
        const int d = lane*4 + s*128;
        float4 w4 = *reinterpret_cast<const float4*>(onw + d);
        float* wv=(float*)&w4; float* ov=(float*)&vals[s];
        float4 r;
        float* rv=(float*)&r;
        #pragma unroll
        for (int j=0;j<4;j++) rv[j] = ov[j]*rms*wv[j];
        *reinterpret_cast<float4*>(op + d) = r;
    }
}

// ---------------- host ----------------
extern "C" void kernel_launch(void* const* d_in, const int* in_sizes, int n_in,
                              void* d_out, int out_size)
{
    const float* x      = (const float*)d_in[0];
    const float* Wq     = (const float*)d_in[1];
    const float* Wk     = (const float*)d_in[2];
    const float* Wv     = (const float*)d_in[3];
    const float* cqw    = (const float*)d_in[4];
    const float* ckw    = (const float*)d_in[5];
    const float* cvw    = (const float*)d_in[6];
    const float* Wb     = (const float*)d_in[7];
    const float* Wds    = (const float*)d_in[8];
    const float* bds    = (const float*)d_in[9];
    const float* Wdl    = (const float*)d_in[10];
    const float* bdl    = (const float*)d_in[11];
    const float* Wtrunk = (const float*)d_in[12];
    const float* btrunk = (const float*)d_in[13];
    const float* Wcoarse= (const float*)d_in[14];
    const float* bcoarse= (const float*)d_in[15];
    const float* Wlocal = (const float*)d_in[16];
    const float* blocal = (const float*)d_in[17];
    const float* Wglobal= (const float*)d_in[18];
    const float* bglobal= (const float*)d_in[19];
    const float* ltc    = (const float*)d_in[20];
    const float* ltf    = (const float*)d_in[21];
    const float* onw    = (const float*)d_in[22];
    const float* Wo     = (const float*)d_in[23];
    float* out = (float*)d_out;

    float* arena;
    cudaGetSymbolAddress((void**)&arena, g_arena);
    float* qpre = arena + OFF_QPRE;
    float* kpre = arena + OFF_KPRE;
    float* vpre = arena + OFF_VPRE;
    float* qb   = arena + OFF_Q;
    float* kb   = arena + OFF_K;
    float* vb   = arena + OFF_V;
    float* ub   = arena + OFF_U;
    float* wb   = arena + OFF_W;
    float* dlt  = arena + OFF_DELTA;
    float* emas = arena + OFF_EMAS;
    float* emal = arena + OFF_EMAL;
    float* omix = arena + OFF_OMIX;
    float* zb   = arena + OFF_Z;
    float* attn = arena + OFF_ATTN;
    float* beta = arena + OFF_BETA;
    float* gs   = arena + OFF_GS;
    float* gl   = arena + OFF_GL;
    float* wgt  = arena + OFF_WGT;

    cudaFuncSetAttribute(megagemm_kernel,  cudaFuncAttributeMaxDynamicSharedMemorySize, GEMM_SMEM_BYTES);
    cudaFuncSetAttribute(gemm_tf32_kernel, cudaFuncAttributeMaxDynamicSharedMemorySize, GEMM_SMEM_BYTES);
    cudaFuncSetAttribute(chunk_pre_kernel, cudaFuncAttributeMaxDynamicSharedMemorySize, PRE_SMEM_BYTES);
    cudaFuncSetAttribute(scan_ema_kernel,  cudaFuncAttributeMaxDynamicSharedMemorySize, SCAN_SMEM_BYTES);

    dim3 blk(256);

    // fused Q/K/V/trunk projections
    megagemm_kernel<<<dim3(56, MROWS/GBM), blk, GEMM_SMEM_BYTES>>>(
        x, Wq, Wk, Wv, Wtrunk, btrunk, qpre, kpre, vpre, zb);

    // beta / decays
    smallproj_kernel<<<MROWS, blk>>>(x, Wb, Wds, bds, Wdl, bdl, beta, gs, gl);

    // conv + silu + relayout (float4)
    conv_silu_kernel<<<MROWS, blk>>>(qpre, kpre, vpre, cqw, ckw, cvw, qb, kb, vb);

    // gate heads (zb ready from megagemm)
    gate_head_kernel<<<MROWS, blk>>>(zb, Wcoarse, bcoarse, Wlocal, blocal,
                                     Wglobal, bglobal, ltc, ltf, wgt);

    // delta rule precompute
    chunk_pre_kernel<<<2048, blk, PRE_SMEM_BYTES>>>(qb, kb, vb, beta, ub, wb, attn);

    // fused scan + EMA (144 blocks = one wave)
    scan_ema_kernel<<<144, blk, SCAN_SMEM_BYTES>>>(qb, kb, ub, wb, attn, dlt,
                                                   vb, gs, gl, emas, emal);

    // combine + RMSNorm
    combine_kernel<<<MROWS/2, blk>>>(vb, emas, emal, dlt, wgt, onw, omix);

    // output projection
    gemm_tf32_kernel<<<dim3(1024/GBN, MROWS/GBM), blk, GEMM_SMEM_BYTES>>>(omix, Wo, out, 1024, 1024);
}

// round 8
// speedup vs baseline: 1.1932x; 1.1000x over previous
#include <cuda_runtime.h>
#include <math.h>
#include <mma.h>

using namespace nvcuda;

#define Hq   4
#define Lq   4096
#define Dq   1024
#define CHK  32
#define NCHK 128
#define MROWS 16384

// ---------------- scratch arena ----------------
constexpr size_t SZf      = 16777216ull;
constexpr size_t OFF_QPRE = 0;
constexpr size_t OFF_U    = 0;
constexpr size_t OFF_KPRE = SZf;
constexpr size_t OFF_W    = SZf;
constexpr size_t OFF_VPRE = 2*SZf;
constexpr size_t OFF_DELTA= 2*SZf;
constexpr size_t OFF_Q    = 3*SZf;
constexpr size_t OFF_K    = 4*SZf;
constexpr size_t OFF_V    = 5*SZf;
constexpr size_t OFF_EMAS = 6*SZf;
constexpr size_t OFF_EMAL = 7*SZf;
constexpr size_t OFF_OMIX = 8*SZf;
constexpr size_t OFF_Z    = 9*SZf;
constexpr size_t OFF_ATTN = OFF_Z + 8388608ull;
constexpr size_t OFF_BETA = OFF_ATTN + 2097152ull;
constexpr size_t OFF_GS   = OFF_BETA + 65536ull;
constexpr size_t OFF_GL   = OFF_GS + 65536ull;
constexpr size_t OFF_WGT  = OFF_GL + 65536ull;
constexpr size_t ARENA_TOTAL = OFF_WGT + 262144ull;

__device__ float g_arena[ARENA_TOTAL];

// chunk_pre smem: qs,ks,vs (32x264) + att,Lm,Ti (32x36) + bs
constexpr int QLD = 264;
constexpr int PRE_SMEM_FLOATS = 3*32*QLD + 3*32*36 + 32;  // 28832
constexpr int PRE_SMEM_BYTES  = PRE_SMEM_FLOATS*4;        // 115328

// scan smem
constexpr int SLD = 36;
constexpr int SCAN_SMEM_FLOATS = 3*256*SLD + 3*32*SLD;
constexpr int SCAN_SMEM_BYTES  = SCAN_SMEM_FLOATS * 4;    // 124416

// GEMM tiling (proven config): 128x64, BK=32, 2-stage
constexpr int GBM = 128, GBN = 64, GBK = 32, GAP = 36;
constexpr int GSTAGE = (GBM+GBN)*GAP;
constexpr int GEMM_SMEM_BYTES = 2*GSTAGE*4;               // 55296

constexpr int GATE_SMEM_BYTES = 24*512*4;                 // 49152
constexpr int SP_SMEM_BYTES   = 12*1024*4;                // 49152

__device__ __forceinline__ float sigm(float x){ return 1.f/(1.f+expf(-x)); }
__device__ __forceinline__ float silu(float x){ return x/(1.f+expf(-x)); }

__device__ __forceinline__ float warp_sum(float v){
    #pragma unroll
    for (int o=16;o>0;o>>=1) v += __shfl_xor_sync(0xffffffffu, v, o);
    return v;
}

__device__ __forceinline__ void cp16(float* s, const float* g){
    unsigned a = (unsigned)__cvta_generic_to_shared(s);
    asm volatile("cp.async.cg.shared.global [%0], [%1], 16;" :: "r"(a), "l"(g));
}

// ---------------- GEMM core: C[M,N]=A@W^T, 128x64 tile ------
__device__ __forceinline__ void gemm_body(const float* __restrict__ A, const float* __restrict__ W,
                                          const float* __restrict__ bias, float* __restrict__ C,
                                          int N, int K, int act, int m0, int n0, float* smem)
{
    const int tid = threadIdx.x, warp = tid>>5;
    const int tr = warp>>1, tcw = warp&1;
    const int lr = tid>>3, lc = (tid&7)*4;

    wmma::fragment<wmma::accumulator,16,16,8,float> acc[2][2];
    #pragma unroll
    for(int i=0;i<2;i++)
        #pragma unroll
        for(int j=0;j<2;j++) wmma::fill_fragment(acc[i][j], 0.f);

    const int KT = K/GBK;

    {
        float* As = smem;
        float* Ws = As + GBM*GAP;
        #pragma unroll
        for (int s=0;s<4;s++){
            int r = lr + s*32;
            cp16(&As[r*GAP+lc], &A[(size_t)(m0+r)*K + lc]);
        }
        #pragma unroll
        for (int s=0;s<2;s++){
            int r = lr + s*32;
            cp16(&Ws[r*GAP+lc], &W[(size_t)(n0+r)*K + lc]);
        }
        asm volatile("cp.async.commit_group;");
    }

    int buf = 0;
    for (int it=0; it<KT; ++it){
        if (it+1 < KT){
            float* As = smem + (buf^1)*GSTAGE;
            float* Ws = As + GBM*GAP;
            const int k0 = (it+1)*GBK;
            #pragma unroll
            for (int s=0;s<4;s++){
                int r = lr + s*32;
                cp16(&As[r*GAP+lc], &A[(size_t)(m0+r)*K + k0 + lc]);
            }
            #pragma unroll
            for (int s=0;s<2;s++){
                int r = lr + s*32;
                cp16(&Ws[r*GAP+lc], &W[(size_t)(n0+r)*K + k0 + lc]);
            }
            asm volatile("cp.async.commit_group;");
            asm volatile("cp.async.wait_group 1;");
        } else {
            asm volatile("cp.async.wait_group 0;");
        }
        __syncthreads();

        float* As = smem + buf*GSTAGE;
        float* Ws = As + GBM*GAP;
        #pragma unroll
        for (int kk=0; kk<GBK; kk+=8){
            wmma::fragment<wmma::matrix_a,16,16,8,wmma::precision::tf32,wmma::row_major> af[2];
            wmma::fragment<wmma::matrix_b,16,16,8,wmma::precision::tf32,wmma::col_major> bf[2];
            #pragma unroll
            for (int i=0;i<2;i++){
                wmma::load_matrix_sync(af[i], &As[(tr*32+i*16)*GAP + kk], GAP);
                #pragma unroll
                for (int t=0;t<af[i].num_elements;t++) af[i].x[t] = wmma::__float_to_tf32(af[i].x[t]);
            }
            #pragma unroll
            for (int j=0;j<2;j++){
                wmma::load_matrix_sync(bf[j], &Ws[(tcw*32+j*16)*GAP + kk], GAP);
                #pragma unroll
                for (int t=0;t<bf[j].num_elements;t++) bf[j].x[t] = wmma::__float_to_tf32(bf[j].x[t]);
            }
            #pragma unroll
            for (int i=0;i<2;i++)
                #pragma unroll
                for (int j=0;j<2;j++)
                    wmma::mma_sync(acc[i][j], af[i], bf[j], acc[i][j]);
        }
        __syncthreads();
        buf ^= 1;
    }

    float* Cs = smem;
    #pragma unroll
    for (int i=0;i<2;i++)
        #pragma unroll
        for (int j=0;j<2;j++)
            wmma::store_matrix_sync(&Cs[(tr*32+i*16)*72 + tcw*32 + j*16], acc[i][j], 72, wmma::mem_row_major);
    __syncthreads();

    for (int idx = tid; idx < GBM*GBN/4; idx += 256){
        int row = idx >> 4, col = (idx & 15)*4;
        float4 v4 = *reinterpret_cast<float4*>(&Cs[row*72 + col]);
        float* vv = (float*)&v4;
        #pragma unroll
        for (int j=0;j<4;j++){
            float v = vv[j];
            if (bias) v += bias[n0+col+j];
            if (act==1) v = v/(1.f+expf(-v));
            vv[j] = v;
        }
        *reinterpret_cast<float4*>(&C[(size_t)(m0+row)*N + n0+col]) = v4;
    }
}

// ---------------- mega GEMM: Q | K | V | trunk fused ----------
__global__ void megagemm_kernel(const float* __restrict__ x,
                                const float* __restrict__ Wq, const float* __restrict__ Wk,
                                const float* __restrict__ Wv, const float* __restrict__ Wt,
                                const float* __restrict__ bt,
                                float* __restrict__ qpre, float* __restrict__ kpre,
                                float* __restrict__ vpre, float* __restrict__ zb)
{
    extern __shared__ float smem[];
    const int bx = blockIdx.x;
    const int m0 = blockIdx.y*GBM;
    const float* W; float* C; const float* bias = nullptr;
    int N, act = 0, nb;
    if (bx < 16)      { W = Wq; C = qpre; N = 1024; nb = bx; }
    else if (bx < 32) { W = Wk; C = kpre; N = 1024; nb = bx-16; }
    else if (bx < 48) { W = Wv; C = vpre; N = 1024; nb = bx-32; }
    else              { W = Wt; C = zb;   N = 512;  nb = bx-48; bias = bt; act = 1; }
    gemm_body(x, W, bias, C, N, 1024, act, m0, nb*GBN, smem);
}

__global__ void gemm_tf32_kernel(const float* __restrict__ A, const float* __restrict__ W,
                                 float* __restrict__ C, int N, int K)
{
    extern __shared__ float smem[];
    gemm_body(A, W, nullptr, C, N, K, 0, blockIdx.y*GBM, blockIdx.x*GBN, smem);
}

// ---------------- causal depthwise conv (k=4) + SiLU, float4, relayout ------
__global__ void conv_silu_kernel(const float* __restrict__ qp, const float* __restrict__ kp,
                                 const float* __restrict__ vp,
                                 const float* __restrict__ wq, const float* __restrict__ wk,
                                 const float* __restrict__ wv,
                                 float* __restrict__ qo, float* __restrict__ ko,
                                 float* __restrict__ vo)
{
    const int row = blockIdx.x;
    const int d4  = threadIdx.x * 4;
    const int l = row & (Lq-1), b = row >> 12;

    float4 wq_c[4], wk_c[4], wv_c[4];
    #pragma unroll
    for (int c=0;c<4;c++){
        wq_c[c] = *reinterpret_cast<const float4*>(wq + (d4+c)*4);
        wk_c[c] = *reinterpret_cast<const float4*>(wk + (d4+c)*4);
        wv_c[c] = *reinterpret_cast<const float4*>(wv + (d4+c)*4);
    }

    float aq[4] = {0,0,0,0}, ak[4] = {0,0,0,0}, av[4] = {0,0,0,0};
    #pragma unroll
    for (int j=0;j<4;j++){
        if (l - 3 + j >= 0){
            size_t idx = (size_t)(row - 3 + j)*Dq + d4;
            float4 xq = *reinterpret_cast<const float4*>(qp + idx);
            float4 xk = *reinterpret_cast<const float4*>(kp + idx);
            float4 xv = *reinterpret_cast<const float4*>(vp + idx);
            const float* xqf = (const float*)&xq;
            const float* xkf = (const float*)&xk;
            const float* xvf = (const float*)&xv;
            #pragma unroll
            for (int c=0;c<4;c++){
                aq[c] = fmaf(xqf[c], ((const float*)&wq_c[c])[j], aq[c]);
                ak[c] = fmaf(xkf[c], ((const float*)&wk_c[c])[j], ak[c]);
                av[c] = fmaf(xvf[c], ((const float*)&wv_c[c])[j], av[c]);
            }
        }
    }
    const int h = d4 >> 8, dk = d4 & 255;
    size_t o = ((size_t)(b*Hq + h)*Lq + l)*256 + dk;
    float4 oq, ok, ov;
    float* oqf = (float*)&oq; float* okf = (float*)&ok; float* ovf = (float*)&ov;
    #pragma unroll
    for (int c=0;c<4;c++){
        oqf[c] = silu(aq[c]);
        okf[c] = silu(ak[c]);
        ovf[c] = silu(av[c]);
    }
    *reinterpret_cast<float4*>(qo + o) = oq;
    *reinterpret_cast<float4*>(ko + o) = ok;
    *reinterpret_cast<float4*>(vo + o) = ov;
}

// ---------------- beta/gs/gl: warp-per-row, weights in smem ----------------
__global__ void smallproj_kernel(const float* __restrict__ x,
                                 const float* __restrict__ Wb, const float* __restrict__ Wds,
                                 const float* __restrict__ bds, const float* __restrict__ Wdl,
                                 const float* __restrict__ bdl,
                                 float* __restrict__ beta, float* __restrict__ gs,
                                 float* __restrict__ gl)
{
    extern __shared__ float Ws[];   // [12][1024]: Wb 0-3, Wds 4-7, Wdl 8-11
    const int tid = threadIdx.x, lane = tid&31, warp = tid>>5;
    for (int idx = tid; idx < 12*256; idx += 256){
        int r = idx >> 8, c4 = (idx & 255)*4;
        const float* src = (r<4) ? Wb + r*1024 + c4 :
                           (r<8) ? Wds + (r-4)*1024 + c4 : Wdl + (r-8)*1024 + c4;
        *reinterpret_cast<float4*>(&Ws[r*1024 + c4]) = *reinterpret_cast<const float4*>(src);
    }
    __syncthreads();

    const int row = blockIdx.x*8 + warp;
    const float* xr = x + (size_t)row*Dq;
    float acc[12];
    #pragma unroll
    for (int r=0;r<12;r++) acc[r]=0.f;
    for (int j=lane; j<1024; j+=32){
        float xv = xr[j];
        #pragma unroll
        for (int r=0;r<12;r++) acc[r] = fmaf(xv, Ws[r*1024+j], acc[r]);
    }
    #pragma unroll
    for (int r=0;r<12;r++) acc[r] = warp_sum(acc[r]);

    if (lane < 12){
        const int h = lane & 3;
        const int b = row >> 12, l = row & (Lq-1);
        size_t o = (size_t)(b*4 + h)*Lq + l;
        if (lane < 4)      beta[o] = sigm(acc[h]);
        else if (lane < 8) gs[o]   = sigm(acc[4+h] + bds[h]);
        else               gl[o]   = sigm(acc[8+h] + bdl[h]);
    }
}

// ---------------- delta-rule per-chunk precompute (wmma) ----------------
__global__ void chunk_pre_kernel(float* __restrict__ q, float* __restrict__ k,
                                 const float* __restrict__ v, const float* __restrict__ beta,
                                 float* __restrict__ u, float* __restrict__ w,
                                 float* __restrict__ attn)
{
    extern __shared__ float sm[];
    float* qs  = sm;                 // 32*264
    float* ks  = qs + 32*QLD;
    float* vs  = ks + 32*QLD;
    float* att = vs + 32*QLD;        // 32*36
    float* Lm  = att+ 32*36;
    float* Ti  = Lm + 32*36;
    float* bs  = Ti + 32*36;         // 32
    const int bh = blockIdx.x >> 7, c = blockIdx.x & 127;
    const int tid = threadIdx.x, lane = tid&31, wid = tid>>5;
    const size_t base = (size_t)bh*Lq + (size_t)c*CHK;

    // load (float4)
    for (int idx = tid; idx < 32*64; idx += 256){
        int i = idx >> 6, d4 = (idx & 63)*4;
        size_t g = (base+i)*256 + d4;
        *reinterpret_cast<float4*>(&qs[i*QLD+d4]) = *reinterpret_cast<const float4*>(&q[g]);
        *reinterpret_cast<float4*>(&ks[i*QLD+d4]) = *reinterpret_cast<const float4*>(&k[g]);
        *reinterpret_cast<float4*>(&vs[i*QLD+d4]) = *reinterpret_cast<const float4*>(&v[g]);
    }
    if (tid < 32) bs[tid] = beta[base + tid];
    __syncthreads();

    // l2norm rows (warp wid -> rows wid*4..wid*4+3)
    #pragma unroll
    for (int r=0;r<4;r++){
        int i = wid*4 + r;
        float sq=0.f, sk=0.f;
        for (int d=lane; d<256; d+=32){
            float a=qs[i*QLD+d]; sq=fmaf(a,a,sq);
            float bb=ks[i*QLD+d]; sk=fmaf(bb,bb,sk);
        }
        sq = warp_sum(sq); sk = warp_sum(sk);
        float rq = rsqrtf(sq + 1e-6f), rk = rsqrtf(sk + 1e-6f);
        for (int d=lane; d<256; d+=32){ qs[i*QLD+d]*=rq; ks[i*QLD+d]*=rk; }
    }
    __syncthreads();

    // write back normalized q,k (float4); scale v by beta in smem
    for (int idx = tid; idx < 32*64; idx += 256){
        int i = idx>>6, d4 = (idx&63)*4;
        size_t g = (base+i)*256 + d4;
        *reinterpret_cast<float4*>(&q[g]) = *reinterpret_cast<float4*>(&qs[i*QLD+d4]);
        *reinterpret_cast<float4*>(&k[g]) = *reinterpret_cast<float4*>(&ks[i*QLD+d4]);
        float b = bs[i];
        float4 vv = *reinterpret_cast<float4*>(&vs[i*QLD+d4]);
        vv.x*=b; vv.y*=b; vv.z*=b; vv.w*=b;
        *reinterpret_cast<float4*>(&vs[i*QLD+d4]) = vv;
    }
    __syncthreads();

    // wmma: att_raw = q@k^T (warps 0-3), Lm_raw = k@k^T (warps 4-7)
    {
        const int ww = wid & 3;
        const int j0 = (ww & 1)*16, i0 = (ww >> 1)*16;
        const float* Asrc = (wid < 4) ? qs : ks;
        float* dst = (wid < 4) ? att : Lm;
        wmma::fragment<wmma::accumulator,16,16,8,float> acc;
        wmma::fill_fragment(acc, 0.f);
        #pragma unroll 4
        for (int dk0 = 0; dk0 < 256; dk0 += 8){
            wmma::fragment<wmma::matrix_a,16,16,8,wmma::precision::tf32,wmma::row_major> af;
            wmma::load_matrix_sync(af, Asrc + i0*QLD + dk0, QLD);
            #pragma unroll
            for (int t=0;t<af.num_elements;t++) af.x[t] = wmma::__float_to_tf32(af.x[t]);
            wmma::fragment<wmma::matrix_b,16,16,8,wmma::precision::tf32,wmma::col_major> bf;
            wmma::load_matrix_sync(bf, ks + j0*QLD + dk0, QLD);
            #pragma unroll
            for (int t=0;t<bf.num_elements;t++) bf.x[t] = wmma::__float_to_tf32(bf.x[t]);
            wmma::mma_sync(acc, af, bf, acc);
        }
        wmma::store_matrix_sync(dst + i0*36 + j0, acc, 36, wmma::mem_row_major);
    }
    __syncthreads();

    // mask/scale: attn out, Lm strict-lower*beta
    for (int idx = tid; idx < 1024; idx += 256){
        int i = idx>>5, j = idx&31;
        attn[(size_t)blockIdx.x*1024 + idx] = (j <= i) ? att[i*36+j] : 0.f;
        Lm[i*36+j] = (j < i) ? bs[i]*Lm[i*36+j] : 0.f;
    }
    __syncthreads();

    // Tinv = (I+Lm)^{-1} forward substitution (warp 0)
    if (wid == 0){
        for (int i=0;i<32;i++){
            float xv = (lane==i) ? 1.f : 0.f;
            for (int p=0;p<i;p++) xv = fmaf(-Lm[i*36+p], Ti[p*36+lane], xv);
            Ti[i*36+lane] = xv;
            __syncwarp();
        }
    }
    __syncthreads();

    // Tib = Ti * beta[col] -> att (reuse)
    for (int idx = tid; idx < 1024; idx += 256){
        int i = idx>>5, j = idx&31;
        att[i*36+j] = Ti[i*36+j]*bs[j];
    }
    __syncthreads();

    // u = Ti@vs , w = Tib@ks : 64 (16x16) tiles over 8 warps
    #pragma unroll
    for (int t = 0; t < 8; t++){
        const int id = wid*8 + t;
        const bool isU = id < 32;
        const int tile = isU ? id : id - 32;
        const int i0 = (tile & 1)*16;
        const int j0 = (tile >> 1)*16;
        const float* A = isU ? Ti : att;
        const float* B = isU ? vs : ks;
        float* C = isU ? u : w;
        wmma::fragment<wmma::accumulator,16,16,8,float> acc;
        wmma::fill_fragment(acc, 0.f);
        #pragma unroll
        for (int m0 = 0; m0 < 32; m0 += 8){
            wmma::fragment<wmma::matrix_a,16,16,8,wmma::precision::tf32,wmma::row_major> af;
            wmma::load_matrix_sync(af, A + i0*36 + m0, 36);
            #pragma unroll
            for (int tt=0;tt<af.num_elements;tt++) af.x[tt] = wmma::__float_to_tf32(af.x[tt]);
            wmma::fragment<wmma::matrix_b,16,16,8,wmma::precision::tf32,wmma::row_major> bf;
            wmma::load_matrix_sync(bf, B + m0*QLD + j0, QLD);
            #pragma unroll
            for (int tt=0;tt<bf.num_elements;tt++) bf.x[tt] = wmma::__float_to_tf32(bf.x[tt]);
            wmma::mma_sync(acc, af, bf, acc);
        }
        wmma::store_matrix_sync(C + (base+i0)*256 + j0, acc, 256, wmma::mem_row_major);
    }
}

// ---------------- fused: delta-scan (0-127) + dual EMA (128-143) ----
__global__ void scan_ema_kernel(const float* __restrict__ q, const float* __restrict__ k,
                                const float* __restrict__ u, const float* __restrict__ w,
                                const float* __restrict__ attn, float* __restrict__ o,
                                const float* __restrict__ v, const float* __restrict__ gs,
                                const float* __restrict__ gl,
                                float* __restrict__ es, float* __restrict__ el)
{
    if (blockIdx.x >= 128){
        const int bh = blockIdx.x - 128;
        const int dv = threadIdx.x;
        const size_t vbase = (size_t)bh*Lq*256 + dv;
        const float* gsp = gs + (size_t)bh*Lq;
        const float* glp = gl + (size_t)bh*Lq;
        float ss = 0.f, sl = 0.f;
        #pragma unroll 8
        for (int t=0;t<Lq;t++){
            float vv = v[vbase + (size_t)t*256];
            float a = gsp[t], b2 = glp[t];
            ss = fmaf(a, ss, (1.f-a)*vv);
            sl = fmaf(b2, sl, (1.f-b2)*vv);
            es[vbase + (size_t)t*256] = ss;
            el[vbase + (size_t)t*256] = sl;
        }
        return;
    }

    extern __shared__ float sm[];
    float* S   = sm;
    float* Shi = S   + 256*SLD;
    float* Slo = Shi + 256*SLD;
    float* uh  = Slo + 256*SLD;
    float* uhh = uh  + 32*SLD;
    float* uhl = uhh + 32*SLD;
    const int bh = blockIdx.x >> 3;
    const int d0 = (blockIdx.x & 7) * 32;
    const int tid = threadIdx.x, warp = tid >> 5;

    for (int i = tid; i < 3*256*SLD; i += 256) sm[i] = 0.f;
    __syncthreads();

    wmma::fragment<wmma::accumulator,16,16,8,float> acc2;

    for (int c = 0; c < NCHK; ++c){
        const size_t base = (size_t)bh*Lq + (size_t)c*32;
        const float* qg = q + base*256;
        const float* kg = k + base*256;
        const float* wg = w + base*256;
        const float* ug = u + base*256 + d0;
        const float* ag = attn + ((size_t)bh*NCHK + c)*1024;
        float*       og = o + base*256 + d0;

        for (int idx = tid; idx < 256*32; idx += 256){
            int r = idx >> 5, cc = idx & 31;
            float s = S[r*SLD + cc];
            float hi = __uint_as_float(__float_as_uint(s) & 0xFFFFE000u);
            Shi[r*SLD + cc] = hi;
            Slo[r*SLD + cc] = wmma::__float_to_tf32(s - hi);
        }
        __syncthreads();

        if (warp < 4){
            const int i0 = (warp & 1)*16, j0 = (warp >> 1)*16;
            wmma::fragment<wmma::accumulator,16,16,8,float> acc;
            wmma::load_matrix_sync(acc, ug + (size_t)i0*256 + j0, 256, wmma::mem_row_major);
            #pragma unroll 4
            for (int dk0 = 0; dk0 < 256; dk0 += 8){
                wmma::fragment<wmma::matrix_a,16,16,8,wmma::precision::tf32,wmma::row_major> af;
                wmma::load_matrix_sync(af, wg + (size_t)i0*256 + dk0, 256);
                #pragma unroll
                for (int t=0;t<af.num_elements;t++) af.x[t] = wmma::__float_to_tf32(-af.x[t]);
                wmma::fragment<wmma::matrix_b,16,16,8,wmma::precision::tf32,wmma::row_major> bf;
                wmma::load_matrix_sync(bf, Shi + dk0*SLD + j0, SLD);
                wmma::mma_sync(acc, af, bf, acc);
                wmma::load_matrix_sync(bf, Slo + dk0*SLD + j0, SLD);
                wmma::mma_sync(acc, af, bf, acc);
            }
            wmma::store_matrix_sync(uh + i0*SLD + j0, acc, SLD, wmma::mem_row_major);
        } else {
            const int i0 = ((warp-4) & 1)*16, j0 = ((warp-4) >> 1)*16;
            wmma::fill_fragment(acc2, 0.f);
            #pragma unroll 4
            for (int dk0 = 0; dk0 < 256; dk0 += 8){
                wmma::fragment<wmma::matrix_a,16,16,8,wmma::precision::tf32,wmma::row_major> af;
                wmma::load_matrix_sync(af, qg + (size_t)i0*256 + dk0, 256);
                #pragma unroll
                for (int t=0;t<af.num_elements;t++) af.x[t] = wmma::__float_to_tf32(af.x[t]);
                wmma::fragment<wmma::matrix_b,16,16,8,wmma::precision::tf32,wmma::row_major> bf;
                wmma::load_matrix_sync(bf, Shi + dk0*SLD + j0, SLD);
                wmma::mma_sync(acc2, af, bf, acc2);
                wmma::load_matrix_sync(bf, Slo + dk0*SLD + j0, SLD);
                wmma::mma_sync(acc2, af, bf, acc2);
            }
        }
        __syncthreads();

        for (int idx = tid; idx < 1024; idx += 256){
            int r = idx >> 5, cc = idx & 31;
            float s = uh[r*SLD + cc];
            float hi = __uint_as_float(__float_as_uint(s) & 0xFFFFE000u);
            uhh[r*SLD + cc] = hi;
            uhl[r*SLD + cc] = wmma::__float_to_tf32(s - hi);
        }
        __syncthreads();

        if (warp < 4){
            #pragma unroll
            for (int t = 0; t < 8; t++){
                const int id = warp*8 + t;
                const int dk0 = (id >> 1)*16, j0 = (id & 1)*16;
                wmma::fragment<wmma::accumulator,16,16,8,float> acc;
                wmma::load_matrix_sync(acc, S + dk0*SLD + j0, SLD, wmma::mem_row_major);
                #pragma unroll
                for (int i2 = 0; i2 < 32; i2 += 8){
                    wmma::fragment<wmma::matrix_a,16,16,8,wmma::precision::tf32,wmma::col_major> af;
                    wmma::load_matrix_sync(af, kg + (size_t)i2*256 + dk0, 256);
                    #pragma unroll
                    for (int tt=0;tt<af.num_elements;tt++) af.x[tt] = wmma::__float_to_tf32(af.x[tt]);
                    wmma::fragment<wmma::matrix_b,16,16,8,wmma::precision::tf32,wmma::row_major> bf;
                    wmma::load_matrix_sync(bf, uhh + i2*SLD + j0, SLD);
                    wmma::mma_sync(acc, af, bf, acc);
                    wmma::load_matrix_sync(bf, uhl + i2*SLD + j0, SLD);
                    wmma::mma_sync(acc, af, bf, acc);
                }
                wmma::store_matrix_sync(S + dk0*SLD + j0, acc, SLD, wmma::mem_row_major);
            }
        } else {
            const int i0 = ((warp-4) & 1)*16, j0 = ((warp-4) >> 1)*16;
            #pragma unroll
            for (int i2 = 0; i2 < 32; i2 += 8){
                wmma::fragment<wmma::matrix_a,16,16,8,wmma::precision::tf32,wmma::row_major> af;
                wmma::load_matrix_sync(af, ag + i0*32 + i2, 32);
                #pragma unroll
                for (int tt=0;tt<af.num_elements;tt++) af.x[tt] = wmma::__float_to_tf32(af.x[tt]);
                wmma::fragment<wmma::matrix_b,16,16,8,wmma::precision::tf32,wmma::row_major> bf;
                wmma::load_matrix_sync(bf, uhh + i2*SLD + j0, SLD);
                wmma::mma_sync(acc2, af, bf, acc2);
                wmma::load_matrix_sync(bf, uhl + i2*SLD + j0, SLD);
                wmma::mma_sync(acc2, af, bf, acc2);
            }
            wmma::store_matrix_sync(og + (size_t)i0*256 + j0, acc2, 256, wmma::mem_row_major);
        }
        __syncthreads();
    }
}

// ---------------- gate heads: warp-per-row, weights in smem ----------------
__global__ void gate_head_kernel(const float* __restrict__ z,
                                 const float* __restrict__ Wc, const float* __restrict__ bc,
                                 const float* __restrict__ Wl, const float* __restrict__ bl,
                                 const float* __restrict__ Wg, const float* __restrict__ bg,
                                 const float* __restrict__ ltc, const float* __restrict__ ltf,
                                 float* __restrict__ wgt)
{
    extern __shared__ float Ws[];   // [24][512]: Wc 0-7, Wl 8-15, Wg 16-23
    const int tid = threadIdx.x, lane = tid&31, warp = tid>>5;
    for (int idx = tid; idx < 24*128; idx += 256){
        int r = idx >> 7, c4 = (idx & 127)*4;
        const float* src = (r<8) ? Wc + r*512 + c4 :
                           (r<16)? Wl + (r-8)*512 + c4 : Wg + (r-16)*512 + c4;
        *reinterpret_cast<float4*>(&Ws[r*512 + c4]) = *reinterpret_cast<const float4*>(src);
    }
    __syncthreads();

    const int row = blockIdx.x*8 + warp;
    const float* zr = z + (size_t)row*512;
    float acc[24];
    #pragma unroll
    for (int r=0;r<24;r++) acc[r]=0.f;
    for (int j=lane; j<512; j+=32){
        float zv = zr[j];
        #pragma unroll
        for (int r=0;r<24;r++) acc[r] = fmaf(zv, Ws[r*512+j], acc[r]);
    }
    #pragma unroll
    for (int r=0;r<24;r++) acc[r] = warp_sum(acc[r]);

    if (lane < 4){
        const int h = lane;
        float tc = log1pf(expf(ltc[h])) + 1e-4f;
        float tf = log1pf(expf(ltf[h])) + 1e-4f;
        float c0 = acc[2*h]+bc[2*h],      c1 = acc[2*h+1]+bc[2*h+1];
        float l0 = acc[8+2*h]+bl[2*h],    l1 = acc[8+2*h+1]+bl[2*h+1];
        float g0 = acc[16+2*h]+bg[2*h],   g1 = acc[16+2*h+1]+bg[2*h+1];
        float pg0 = sigm((c0-c1)/tc), pg1 = 1.f - pg0;
        float q0  = sigm((l0-l1)/tf), q1 = 1.f - q0;
        float r0  = sigm((g0-g1)/tf), r1 = 1.f - r0;
        size_t o = (size_t)row*16 + h*4;
        wgt[o+0] = pg0*q0; wgt[o+1] = pg0*q1; wgt[o+2] = pg1*r0; wgt[o+3] = pg1*r1;
    }
}

// ---------------- mix + per-head RMSNorm (warp per head-row, float4) --------
__global__ void combine_kernel(const float* __restrict__ v, const float* __restrict__ es,
                               const float* __restrict__ el, const float* __restrict__ dl,
                               const float* __restrict__ wgt, const float* __restrict__ onw,
                               float* __restrict__ omix)
{
    const int gw = blockIdx.x*8 + (threadIdx.x>>5);
    const int row = gw >> 2, h = gw & 3;
    const int b = row >> 12, l = row & (Lq-1);
    const int lane = threadIdx.x & 31;
    const size_t gbase = ((size_t)(b*4+h)*Lq + l)*256;
    const float* wp = wgt + (size_t)row*16 + h*4;
    const float w0 = wp[0], w1 = wp[1], w2 = wp[2], w3 = wp[3];

    float4 vals[2];
    float ss = 0.f;
    #pragma unroll
    for (int s=0;s<2;s++){
        const int d = lane*4 + s*128;
        float4 a = *reinterpret_cast<const float4*>(v  + gbase + d);
        float4 b4= *reinterpret_cast<const float4*>(es + gbase + d);
        float4 c4= *reinterpret_cast<const float4*>(dl + gbase + d);
        float4 d4= *reinterpret_cast<const float4*>(el + gbase + d);
        float* av=(float*)&a; float* bv=(float*)&b4; float* cv=(float*)&c4; float* dv=(float*)&d4;
        float* ov=(float*)&vals[s];
        #pragma unroll
        for (int j=0;j<4;j++){
            float val = w0*av[j] + w1*bv[j] + w2*cv[j] + w3*dv[j];
            ov[j] = val;
            ss = fmaf(val, val, ss);
        }
    }
    ss = warp_sum(ss);
    const float rms = rsqrtf(ss*(1.f/256.f) + 1e-5f);
    float* op = omix + (size_t)row*1024 + h*256;
    #pragma unroll
    for (int s=0;s<2;s++){
        const int d = lane*4 + s*128;
        float4 w4 = *reinterpret_cast<const float4*>(onw + d);
        float* wv=(float*)&w4; float* ov=(float*)&vals[s];
        float4 r;
        float* rv=(float*)&r;
        #pragma unroll
        for (int j=0;j<4;j++) rv[j] = ov[j]*rms*wv[j];
        *reinterpret_cast<float4*>(op + d) = r;
    }
}

// ---------------- host ----------------
extern "C" void kernel_launch(void* const* d_in, const int* in_sizes, int n_in,
                              void* d_out, int out_size)
{
    const float* x      = (const float*)d_in[0];
    const float* Wq     = (const float*)d_in[1];
    const float* Wk     = (const float*)d_in[2];
    const float* Wv     = (const float*)d_in[3];
    const float* cqw    = (const float*)d_in[4];
    const float* ckw    = (const float*)d_in[5];
    const float* cvw    = (const float*)d_in[6];
    const float* Wb     = (const float*)d_in[7];
    const float* Wds    = (const float*)d_in[8];
    const float* bds    = (const float*)d_in[9];
    const float* Wdl    = (const float*)d_in[10];
    const float* bdl    = (const float*)d_in[11];
    const float* Wtrunk = (const float*)d_in[12];
    const float* btrunk = (const float*)d_in[13];
    const float* Wcoarse= (const float*)d_in[14];
    const float* bcoarse= (const float*)d_in[15];
    const float* Wlocal = (const float*)d_in[16];
    const float* blocal = (const float*)d_in[17];
    const float* Wglobal= (const float*)d_in[18];
    const float* bglobal= (const float*)d_in[19];
    const float* ltc    = (const float*)d_in[20];
    const float* ltf    = (const float*)d_in[21];
    const float* onw    = (const float*)d_in[22];
    const float* Wo     = (const float*)d_in[23];
    float* out = (float*)d_out;

    float* arena;
    cudaGetSymbolAddress((void**)&arena, g_arena);
    float* qpre = arena + OFF_QPRE;
    float* kpre = arena + OFF_KPRE;
    float* vpre = arena + OFF_VPRE;
    float* qb   = arena + OFF_Q;
    float* kb   = arena + OFF_K;
    float* vb   = arena + OFF_V;
    float* ub   = arena + OFF_U;
    float* wb   = arena + OFF_W;
    float* dlt  = arena + OFF_DELTA;
    float* emas = arena + OFF_EMAS;
    float* emal = arena + OFF_EMAL;
    float* omix = arena + OFF_OMIX;
    float* zb   = arena + OFF_Z;
    float* attn = arena + OFF_ATTN;
    float* beta = arena + OFF_BETA;
    float* gs   = arena + OFF_GS;
    float* gl   = arena + OFF_GL;
    float* wgt  = arena + OFF_WGT;

    cudaFuncSetAttribute(megagemm_kernel,  cudaFuncAttributeMaxDynamicSharedMemorySize, GEMM_SMEM_BYTES);
    cudaFuncSetAttribute(gemm_tf32_kernel, cudaFuncAttributeMaxDynamicSharedMemorySize, GEMM_SMEM_BYTES);
    cudaFuncSetAttribute(chunk_pre_kernel, cudaFuncAttributeMaxDynamicSharedMemorySize, PRE_SMEM_BYTES);
    cudaFuncSetAttribute(scan_ema_kernel,  cudaFuncAttributeMaxDynamicSharedMemorySize, SCAN_SMEM_BYTES);
    cudaFuncSetAttribute(gate_head_kernel, cudaFuncAttributeMaxDynamicSharedMemorySize, GATE_SMEM_BYTES);
    cudaFuncSetAttribute(smallproj_kernel, cudaFuncAttributeMaxDynamicSharedMemorySize, SP_SMEM_BYTES);

    dim3 blk(256);

    // fused Q/K/V/trunk projections
    megagemm_kernel<<<dim3(56, MROWS/GBM), blk, GEMM_SMEM_BYTES>>>(
        x, Wq, Wk, Wv, Wtrunk, btrunk, qpre, kpre, vpre, zb);

    // beta / decays (warp-per-row, weights in smem)
    smallproj_kernel<<<MROWS/8, blk, SP_SMEM_BYTES>>>(x, Wb, Wds, bds, Wdl, bdl, beta, gs, gl);

    // conv + silu + relayout
    conv_silu_kernel<<<MROWS, blk>>>(qpre, kpre, vpre, cqw, ckw, cvw, qb, kb, vb);

    // gate heads
    gate_head_kernel<<<MROWS/8, blk, GATE_SMEM_BYTES>>>(zb, Wcoarse, bcoarse, Wlocal, blocal,
                                                        Wglobal, bglobal, ltc, ltf, wgt);

    // delta rule precompute (wmma)
    chunk_pre_kernel<<<2048, blk, PRE_SMEM_BYTES>>>(qb, kb, vb, beta, ub, wb, attn);

    // fused scan + EMA
    scan_ema_kernel<<<144, blk, SCAN_SMEM_BYTES>>>(qb, kb, ub, wb, attn, dlt,
                                                   vb, gs, gl, emas, emal);

    // combine + RMSNorm
    combine_kernel<<<MROWS/2, blk>>>(vb, emas, emal, dlt, wgt, onw, omix);

    // output projection
    gemm_tf32_kernel<<<dim3(1024/GBN, MROWS/GBM), blk, GEMM_SMEM_BYTES>>>(omix, Wo, out, 1024, 1024);
}

// round 9
// speedup vs baseline: 1.2148x; 1.0181x over previous
#include <cuda_runtime.h>
#include <math.h>
#include <mma.h>

using namespace nvcuda;

#define Hq   4
#define Lq   4096
#define Dq   1024
#define CHK  32
#define NCHK 128
#define MROWS 16384

// ---------------- scratch arena ----------------
constexpr size_t SZf      = 16777216ull;
constexpr size_t OFF_QPRE = 0;
constexpr size_t OFF_U    = 0;
constexpr size_t OFF_KPRE = SZf;
constexpr size_t OFF_W    = SZf;
constexpr size_t OFF_VPRE = 2*SZf;
constexpr size_t OFF_DELTA= 2*SZf;
constexpr size_t OFF_Q    = 3*SZf;
constexpr size_t OFF_K    = 4*SZf;
constexpr size_t OFF_V    = 5*SZf;
constexpr size_t OFF_EMAS = 6*SZf;
constexpr size_t OFF_EMAL = 7*SZf;
constexpr size_t OFF_OMIX = 8*SZf;
constexpr size_t OFF_Z    = 9*SZf;
constexpr size_t OFF_ATTN = OFF_Z + 8388608ull;
constexpr size_t OFF_BETA = OFF_ATTN + 2097152ull;
constexpr size_t OFF_GS   = OFF_BETA + 65536ull;
constexpr size_t OFF_GL   = OFF_GS + 65536ull;
constexpr size_t OFF_WGT  = OFF_GL + 65536ull;
constexpr size_t OFF_XR   = OFF_WGT + 262144ull;     // rounded x (16M)
constexpr size_t OFF_WQR  = OFF_XR + SZf;
constexpr size_t OFF_WKR  = OFF_WQR + 1048576ull;
constexpr size_t OFF_WVR  = OFF_WKR + 1048576ull;
constexpr size_t OFF_WTR  = OFF_WVR + 1048576ull;
constexpr size_t OFF_WOR  = OFF_WTR + 524288ull;
constexpr size_t ARENA_TOTAL = OFF_WOR + 1048576ull;

__device__ float g_arena[ARENA_TOTAL];

// chunk_pre smem
constexpr int QLD = 264;
constexpr int PRE_SMEM_FLOATS = 3*32*QLD + 3*32*36 + 32;
constexpr int PRE_SMEM_BYTES  = PRE_SMEM_FLOATS*4;        // 115328

// scan smem
constexpr int SLD = 36;
constexpr int SCAN_SMEM_FLOATS = 3*256*SLD + 3*32*SLD;
constexpr int SCAN_SMEM_BYTES  = SCAN_SMEM_FLOATS * 4;    // 124416

// GEMM tiling: 128x64, BK=32, 2-stage
constexpr int GBM = 128, GBN = 64, GBK = 32, GAP = 36;
constexpr int GSTAGE = (GBM+GBN)*GAP;
constexpr int GEMM_SMEM_BYTES = 2*GSTAGE*4;               // 55296

constexpr int GATE_SMEM_BYTES = 24*512*4;                 // 49152
constexpr int SP_SMEM_BYTES   = 12*1024*4;                // 49152

__device__ __forceinline__ float sigm(float x){ return 1.f/(1.f+expf(-x)); }
__device__ __forceinline__ float silu(float x){ return x/(1.f+expf(-x)); }
__device__ __forceinline__ float tf32r(float x){ return wmma::__float_to_tf32(x); }

__device__ __forceinline__ float warp_sum(float v){
    #pragma unroll
    for (int o=16;o>0;o>>=1) v += __shfl_xor_sync(0xffffffffu, v, o);
    return v;
}

__device__ __forceinline__ void cp16(float* s, const float* g){
    unsigned a = (unsigned)__cvta_generic_to_shared(s);
    asm volatile("cp.async.cg.shared.global [%0], [%1], 16;" :: "r"(a), "l"(g));
}

// ---------------- tf32 rounding copy ----------------
__global__ void round_tf32_kernel(const float* __restrict__ src, float* __restrict__ dst, int n4)
{
    int i = blockIdx.x*256 + threadIdx.x;
    if (i < n4){
        float4 v = reinterpret_cast<const float4*>(src)[i];
        v.x = tf32r(v.x); v.y = tf32r(v.y); v.z = tf32r(v.z); v.w = tf32r(v.w);
        reinterpret_cast<float4*>(dst)[i] = v;
    }
}

// ---------------- GEMM core (inputs pre-rounded to tf32, NO cvt) ------------
__device__ __forceinline__ void gemm_body(const float* __restrict__ A, const float* __restrict__ W,
                                          const float* __restrict__ bias, float* __restrict__ C,
                                          int N, int K, int act, int m0, int n0, float* smem)
{
    const int tid = threadIdx.x, warp = tid>>5;
    const int tr = warp>>1, tcw = warp&1;
    const int lr = tid>>3, lc = (tid&7)*4;

    wmma::fragment<wmma::accumulator,16,16,8,float> acc[2][2];
    #pragma unroll
    for(int i=0;i<2;i++)
        #pragma unroll
        for(int j=0;j<2;j++) wmma::fill_fragment(acc[i][j], 0.f);

    const int KT = K/GBK;

    {
        float* As = smem;
        float* Ws = As + GBM*GAP;
        #pragma unroll
        for (int s=0;s<4;s++){
            int r = lr + s*32;
            cp16(&As[r*GAP+lc], &A[(size_t)(m0+r)*K + lc]);
        }
        #pragma unroll
        for (int s=0;s<2;s++){
            int r = lr + s*32;
            cp16(&Ws[r*GAP+lc], &W[(size_t)(n0+r)*K + lc]);
        }
        asm volatile("cp.async.commit_group;");
    }

    int buf = 0;
    for (int it=0; it<KT; ++it){
        if (it+1 < KT){
            float* As = smem + (buf^1)*GSTAGE;
            float* Ws = As + GBM*GAP;
            const int k0 = (it+1)*GBK;
            #pragma unroll
            for (int s=0;s<4;s++){
                int r = lr + s*32;
                cp16(&As[r*GAP+lc], &A[(size_t)(m0+r)*K + k0 + lc]);
            }
            #pragma unroll
            for (int s=0;s<2;s++){
                int r = lr + s*32;
                cp16(&Ws[r*GAP+lc], &W[(size_t)(n0+r)*K + k0 + lc]);
            }
            asm volatile("cp.async.commit_group;");
            asm volatile("cp.async.wait_group 1;");
        } else {
            asm volatile("cp.async.wait_group 0;");
        }
        __syncthreads();

        float* As = smem + buf*GSTAGE;
        float* Ws = As + GBM*GAP;
        #pragma unroll
        for (int kk=0; kk<GBK; kk+=8){
            wmma::fragment<wmma::matrix_a,16,16,8,wmma::precision::tf32,wmma::row_major> af[2];
            wmma::fragment<wmma::matrix_b,16,16,8,wmma::precision::tf32,wmma::col_major> bf[2];
            #pragma unroll
            for (int i=0;i<2;i++)
                wmma::load_matrix_sync(af[i], &As[(tr*32+i*16)*GAP + kk], GAP);
            #pragma unroll
            for (int j=0;j<2;j++)
                wmma::load_matrix_sync(bf[j], &Ws[(tcw*32+j*16)*GAP + kk], GAP);
            #pragma unroll
            for (int i=0;i<2;i++)
                #pragma unroll
                for (int j=0;j<2;j++)
                    wmma::mma_sync(acc[i][j], af[i], bf[j], acc[i][j]);
        }
        __syncthreads();
        buf ^= 1;
    }

    if (!bias && act == 0){
        // direct store to global
        #pragma unroll
        for (int i=0;i<2;i++)
            #pragma unroll
            for (int j=0;j<2;j++)
                wmma::store_matrix_sync(&C[(size_t)(m0+tr*32+i*16)*N + n0 + tcw*32 + j*16],
                                        acc[i][j], N, wmma::mem_row_major);
        return;
    }

    float* Cs = smem;
    #pragma unroll
    for (int i=0;i<2;i++)
        #pragma unroll
        for (int j=0;j<2;j++)
            wmma::store_matrix_sync(&Cs[(tr*32+i*16)*72 + tcw*32 + j*16], acc[i][j], 72, wmma::mem_row_major);
    __syncthreads();

    for (int idx = tid; idx < GBM*GBN/4; idx += 256){
        int row = idx >> 4, col = (idx & 15)*4;
        float4 v4 = *reinterpret_cast<float4*>(&Cs[row*72 + col]);
        float* vv = (float*)&v4;
        #pragma unroll
        for (int j=0;j<4;j++){
            float v = vv[j];
            if (bias) v += bias[n0+col+j];
            if (act==1) v = v/(1.f+expf(-v));
            vv[j] = v;
        }
        *reinterpret_cast<float4*>(&C[(size_t)(m0+row)*N + n0+col]) = v4;
    }
}

// ---------------- mega GEMM: Q | K | V | trunk fused ----------
__global__ void megagemm_kernel(const float* __restrict__ x,
                                const float* __restrict__ Wq, const float* __restrict__ Wk,
                                const float* __restrict__ Wv, const float* __restrict__ Wt,
                                const float* __restrict__ bt,
                                float* __restrict__ qpre, float* __restrict__ kpre,
                                float* __restrict__ vpre, float* __restrict__ zb)
{
    extern __shared__ float smem[];
    const int bx = blockIdx.x;
    const int m0 = blockIdx.y*GBM;
    const float* W; float* C; const float* bias = nullptr;
    int N, act = 0, nb;
    if (bx < 16)      { W = Wq; C = qpre; N = 1024; nb = bx; }
    else if (bx < 32) { W = Wk; C = kpre; N = 1024; nb = bx-16; }
    else if (bx < 48) { W = Wv; C = vpre; N = 1024; nb = bx-32; }
    else              { W = Wt; C = zb;   N = 512;  nb = bx-48; bias = bt; act = 1; }
    gemm_body(x, W, bias, C, N, 1024, act, m0, nb*GBN, smem);
}

__global__ void gemm_tf32_kernel(const float* __restrict__ A, const float* __restrict__ W,
                                 float* __restrict__ C, int N, int K)
{
    extern __shared__ float smem[];
    gemm_body(A, W, nullptr, C, N, K, 0, blockIdx.y*GBM, blockIdx.x*GBN, smem);
}

// ---------------- causal depthwise conv (k=4) + SiLU, float4, relayout ------
__global__ void conv_silu_kernel(const float* __restrict__ qp, const float* __restrict__ kp,
                                 const float* __restrict__ vp,
                                 const float* __restrict__ wq, const float* __restrict__ wk,
                                 const float* __restrict__ wv,
                                 float* __restrict__ qo, float* __restrict__ ko,
                                 float* __restrict__ vo)
{
    const int row = blockIdx.x;
    const int d4  = threadIdx.x * 4;
    const int l = row & (Lq-1), b = row >> 12;

    float4 wq_c[4], wk_c[4], wv_c[4];
    #pragma unroll
    for (int c=0;c<4;c++){
        wq_c[c] = *reinterpret_cast<const float4*>(wq + (d4+c)*4);
        wk_c[c] = *reinterpret_cast<const float4*>(wk + (d4+c)*4);
        wv_c[c] = *reinterpret_cast<const float4*>(wv + (d4+c)*4);
    }

    float aq[4] = {0,0,0,0}, ak[4] = {0,0,0,0}, av[4] = {0,0,0,0};
    #pragma unroll
    for (int j=0;j<4;j++){
        if (l - 3 + j >= 0){
            size_t idx = (size_t)(row - 3 + j)*Dq + d4;
            float4 xq = *reinterpret_cast<const float4*>(qp + idx);
            float4 xk = *reinterpret_cast<const float4*>(kp + idx);
            float4 xv = *reinterpret_cast<const float4*>(vp + idx);
            const float* xqf = (const float*)&xq;
            const float* xkf = (const float*)&xk;
            const float* xvf = (const float*)&xv;
            #pragma unroll
            for (int c=0;c<4;c++){
                aq[c] = fmaf(xqf[c], ((const float*)&wq_c[c])[j], aq[c]);
                ak[c] = fmaf(xkf[c], ((const float*)&wk_c[c])[j], ak[c]);
                av[c] = fmaf(xvf[c], ((const float*)&wv_c[c])[j], av[c]);
            }
        }
    }
    const int h = d4 >> 8, dk = d4 & 255;
    size_t o = ((size_t)(b*Hq + h)*Lq + l)*256 + dk;
    float4 oq, ok, ov;
    float* oqf = (float*)&oq; float* okf = (float*)&ok; float* ovf = (float*)&ov;
    #pragma unroll
    for (int c=0;c<4;c++){
        oqf[c] = silu(aq[c]);
        okf[c] = silu(ak[c]);
        ovf[c] = silu(av[c]);
    }
    *reinterpret_cast<float4*>(qo + o) = oq;
    *reinterpret_cast<float4*>(ko + o) = ok;
    *reinterpret_cast<float4*>(vo + o) = ov;
}

// ---------------- beta/gs/gl: 2 rows per warp, weights in smem ----------------
__global__ void smallproj_kernel(const float* __restrict__ x,
                                 const float* __restrict__ Wb, const float* __restrict__ Wds,
                                 const float* __restrict__ bds, const float* __restrict__ Wdl,
                                 const float* __restrict__ bdl,
                                 float* __restrict__ beta, float* __restrict__ gs,
                                 float* __restrict__ gl)
{
    extern __shared__ float Ws[];   // [12][1024]
    const int tid = threadIdx.x, lane = tid&31, warp = tid>>5;
    for (int idx = tid; idx < 12*256; idx += 256){
        int r = idx >> 8, c4 = (idx & 255)*4;
        const float* src = (r<4) ? Wb + r*1024 + c4 :
                           (r<8) ? Wds + (r-4)*1024 + c4 : Wdl + (r-8)*1024 + c4;
        *reinterpret_cast<float4*>(&Ws[r*1024 + c4]) = *reinterpret_cast<const float4*>(src);
    }
    __syncthreads();

    #pragma unroll
    for (int rr=0; rr<2; rr++){
        const int row = blockIdx.x*16 + warp*2 + rr;
        const float* xr = x + (size_t)row*Dq;
        float acc[12];
        #pragma unroll
        for (int r=0;r<12;r++) acc[r]=0.f;
        for (int j=lane; j<1024; j+=32){
            float xv = xr[j];
            #pragma unroll
            for (int r=0;r<12;r++) acc[r] = fmaf(xv, Ws[r*1024+j], acc[r]);
        }
        #pragma unroll
        for (int r=0;r<12;r++) acc[r] = warp_sum(acc[r]);

        if (lane < 12){
            const int h = lane & 3;
            const int b = row >> 12, l = row & (Lq-1);
            size_t o = (size_t)(b*4 + h)*Lq + l;
            if (lane < 4)      beta[o] = sigm(acc[h]);
            else if (lane < 8) gs[o]   = sigm(acc[4+h] + bds[h]);
            else               gl[o]   = sigm(acc[8+h] + bdl[h]);
        }
    }
}

// ---------------- delta-rule per-chunk precompute (wmma, pre-rounded) -------
__global__ void chunk_pre_kernel(float* __restrict__ q, float* __restrict__ k,
                                 const float* __restrict__ v, const float* __restrict__ beta,
                                 float* __restrict__ u, float* __restrict__ w,
                                 float* __restrict__ attn)
{
    extern __shared__ float sm[];
    float* qs  = sm;                 // 32*264
    float* ks  = qs + 32*QLD;
    float* vs  = ks + 32*QLD;
    float* att = vs + 32*QLD;        // 32*36
    float* Lm  = att+ 32*36;
    float* Ti  = Lm + 32*36;
    float* bs  = Ti + 32*36;
    const int bh = blockIdx.x >> 7, c = blockIdx.x & 127;
    const int tid = threadIdx.x, lane = tid&31, wid = tid>>5;
    const size_t base = (size_t)bh*Lq + (size_t)c*CHK;

    for (int idx = tid; idx < 32*64; idx += 256){
        int i = idx >> 6, d4 = (idx & 63)*4;
        size_t g = (base+i)*256 + d4;
        *reinterpret_cast<float4*>(&qs[i*QLD+d4]) = *reinterpret_cast<const float4*>(&q[g]);
        *reinterpret_cast<float4*>(&ks[i*QLD+d4]) = *reinterpret_cast<const float4*>(&k[g]);
        *reinterpret_cast<float4*>(&vs[i*QLD+d4]) = *reinterpret_cast<const float4*>(&v[g]);
    }
    if (tid < 32) bs[tid] = beta[base + tid];
    __syncthreads();

    // l2norm rows -> round to tf32 in smem
    #pragma unroll
    for (int r=0;r<4;r++){
        int i = wid*4 + r;
        float sq=0.f, sk=0.f;
        for (int d=lane; d<256; d+=32){
            float a=qs[i*QLD+d]; sq=fmaf(a,a,sq);
            float bb=ks[i*QLD+d]; sk=fmaf(bb,bb,sk);
        }
        sq = warp_sum(sq); sk = warp_sum(sk);
        float rq = rsqrtf(sq + 1e-6f), rk = rsqrtf(sk + 1e-6f);
        for (int d=lane; d<256; d+=32){
            qs[i*QLD+d] = tf32r(qs[i*QLD+d]*rq);
            ks[i*QLD+d] = tf32r(ks[i*QLD+d]*rk);
        }
    }
    __syncthreads();

    // writeback rounded q,k; round v*beta in smem
    for (int idx = tid; idx < 32*64; idx += 256){
        int i = idx>>6, d4 = (idx&63)*4;
        size_t g = (base+i)*256 + d4;
        *reinterpret_cast<float4*>(&q[g]) = *reinterpret_cast<float4*>(&qs[i*QLD+d4]);
        *reinterpret_cast<float4*>(&k[g]) = *reinterpret_cast<float4*>(&ks[i*QLD+d4]);
        float b = bs[i];
        float4 vv = *reinterpret_cast<float4*>(&vs[i*QLD+d4]);
        vv.x = tf32r(vv.x*b); vv.y = tf32r(vv.y*b); vv.z = tf32r(vv.z*b); vv.w = tf32r(vv.w*b);
        *reinterpret_cast<float4*>(&vs[i*QLD+d4]) = vv;
    }
    __syncthreads();

    // wmma: att_raw = q@k^T (warps 0-3), Lm_raw = k@k^T (warps 4-7) — no cvt
    {
        const int ww = wid & 3;
        const int j0 = (ww & 1)*16, i0 = (ww >> 1)*16;
        const float* Asrc = (wid < 4) ? qs : ks;
        float* dst = (wid < 4) ? att : Lm;
        wmma::fragment<wmma::accumulator,16,16,8,float> acc;
        wmma::fill_fragment(acc, 0.f);
        #pragma unroll 4
        for (int dk0 = 0; dk0 < 256; dk0 += 8){
            wmma::fragment<wmma::matrix_a,16,16,8,wmma::precision::tf32,wmma::row_major> af;
            wmma::load_matrix_sync(af, Asrc + i0*QLD + dk0, QLD);
            wmma::fragment<wmma::matrix_b,16,16,8,wmma::precision::tf32,wmma::col_major> bf;
            wmma::load_matrix_sync(bf, ks + j0*QLD + dk0, QLD);
            wmma::mma_sync(acc, af, bf, acc);
        }
        wmma::store_matrix_sync(dst + i0*36 + j0, acc, 36, wmma::mem_row_major);
    }
    __syncthreads();

    // mask/scale: attn out (rounded), Lm strict-lower*beta (fp32 for substitution)
    for (int idx = tid; idx < 1024; idx += 256){
        int i = idx>>5, j = idx&31;
        attn[(size_t)blockIdx.x*1024 + idx] = (j <= i) ? tf32r(att[i*36+j]) : 0.f;
        Lm[i*36+j] = (j < i) ? bs[i]*Lm[i*36+j] : 0.f;
    }
    __syncthreads();

    // Tinv = (I+Lm)^{-1} forward substitution (warp 0, fp32)
    if (wid == 0){
        for (int i=0;i<32;i++){
            float xv = (lane==i) ? 1.f : 0.f;
            for (int p=0;p<i;p++) xv = fmaf(-Lm[i*36+p], Ti[p*36+lane], xv);
            Ti[i*36+lane] = xv;
            __syncwarp();
        }
    }
    __syncthreads();

    // rounded copies: Lm <- round(Ti), att <- round(Ti*beta[col])
    for (int idx = tid; idx < 1024; idx += 256){
        int i = idx>>5, j = idx&31;
        float t = Ti[i*36+j];
        Lm[i*36+j]  = tf32r(t);
        att[i*36+j] = tf32r(t*bs[j]);
    }
    __syncthreads();

    // u = Ti@vs , w = Tib@ks — no cvt
    #pragma unroll
    for (int t = 0; t < 8; t++){
        const int id = wid*8 + t;
        const bool isU = id < 32;
        const int tile = isU ? id : id - 32;
        const int i0 = (tile & 1)*16;
        const int j0 = (tile >> 1)*16;
        const float* A = isU ? Lm : att;
        const float* B = isU ? vs : ks;
        float* C = isU ? u : w;
        wmma::fragment<wmma::accumulator,16,16,8,float> acc;
        wmma::fill_fragment(acc, 0.f);
        #pragma unroll
        for (int m0 = 0; m0 < 32; m0 += 8){
            wmma::fragment<wmma::matrix_a,16,16,8,wmma::precision::tf32,wmma::row_major> af;
            wmma::load_matrix_sync(af, A + i0*36 + m0, 36);
            wmma::fragment<wmma::matrix_b,16,16,8,wmma::precision::tf32,wmma::row_major> bf;
            wmma::load_matrix_sync(bf, B + m0*QLD + j0, QLD);
            wmma::mma_sync(acc, af, bf, acc);
        }
        wmma::store_matrix_sync(C + (base+i0)*256 + j0, acc, 256, wmma::mem_row_major);
    }
}

// ---------------- fused: delta-scan (0-127) + dual EMA (128-143) ----
__global__ void scan_ema_kernel(const float* __restrict__ q, const float* __restrict__ k,
                                const float* __restrict__ u, const float* __restrict__ w,
                                const float* __restrict__ attn, float* __restrict__ o,
                                const float* __restrict__ v, const float* __restrict__ gs,
                                const float* __restrict__ gl,
                                float* __restrict__ es, float* __restrict__ el)
{
    if (blockIdx.x >= 128){
        const int bh = blockIdx.x - 128;
        const int dv = threadIdx.x;
        const size_t vbase = (size_t)bh*Lq*256 + dv;
        const float* gsp = gs + (size_t)bh*Lq;
        const float* glp = gl + (size_t)bh*Lq;
        float ss = 0.f, sl = 0.f;
        #pragma unroll 8
        for (int t=0;t<Lq;t++){
            float vv = v[vbase + (size_t)t*256];
            float a = gsp[t], b2 = glp[t];
            ss = fmaf(a, ss, (1.f-a)*vv);
            sl = fmaf(b2, sl, (1.f-b2)*vv);
            es[vbase + (size_t)t*256] = ss;
            el[vbase + (size_t)t*256] = sl;
        }
        return;
    }

    extern __shared__ float sm[];
    float* S   = sm;
    float* Shi = S   + 256*SLD;
    float* Slo = Shi + 256*SLD;
    float* uh  = Slo + 256*SLD;
    float* uhh = uh  + 32*SLD;
    float* uhl = uhh + 32*SLD;
    const int bh = blockIdx.x >> 3;
    const int d0 = (blockIdx.x & 7) * 32;
    const int tid = threadIdx.x, warp = tid >> 5;

    for (int i = tid; i < 3*256*SLD; i += 256) sm[i] = 0.f;
    __syncthreads();

    wmma::fragment<wmma::accumulator,16,16,8,float> acc2;

    for (int c = 0; c < NCHK; ++c){
        const size_t base = (size_t)bh*Lq + (size_t)c*32;
        const float* qg = q + base*256;
        const float* kg = k + base*256;
        const float* wg = w + base*256;
        const float* ug = u + base*256 + d0;
        const float* ag = attn + ((size_t)bh*NCHK + c)*1024;
        float*       og = o + base*256 + d0;

        for (int idx = tid; idx < 256*32; idx += 256){
            int r = idx >> 5, cc = idx & 31;
            float s = S[r*SLD + cc];
            float hi = __uint_as_float(__float_as_uint(s) & 0xFFFFE000u);
            Shi[r*SLD + cc] = hi;
            Slo[r*SLD + cc] = tf32r(s - hi);
        }
        __syncthreads();

        if (warp < 4){
            const int i0 = (warp & 1)*16, j0 = (warp >> 1)*16;
            wmma::fragment<wmma::accumulator,16,16,8,float> acc;
            wmma::load_matrix_sync(acc, ug + (size_t)i0*256 + j0, 256, wmma::mem_row_major);
            #pragma unroll 4
            for (int dk0 = 0; dk0 < 256; dk0 += 8){
                wmma::fragment<wmma::matrix_a,16,16,8,wmma::precision::tf32,wmma::row_major> af;
                wmma::load_matrix_sync(af, wg + (size_t)i0*256 + dk0, 256);
                #pragma unroll
                for (int t=0;t<af.num_elements;t++) af.x[t] = tf32r(-af.x[t]);
                wmma::fragment<wmma::matrix_b,16,16,8,wmma::precision::tf32,wmma::row_major> bf;
                wmma::load_matrix_sync(bf, Shi + dk0*SLD + j0, SLD);
                wmma::mma_sync(acc, af, bf, acc);
                wmma::load_matrix_sync(bf, Slo + dk0*SLD + j0, SLD);
                wmma::mma_sync(acc, af, bf, acc);
            }
            wmma::store_matrix_sync(uh + i0*SLD + j0, acc, SLD, wmma::mem_row_major);
        } else {
            const int i0 = ((warp-4) & 1)*16, j0 = ((warp-4) >> 1)*16;
            wmma::fill_fragment(acc2, 0.f);
            #pragma unroll 4
            for (int dk0 = 0; dk0 < 256; dk0 += 8){
                wmma::fragment<wmma::matrix_a,16,16,8,wmma::precision::tf32,wmma::row_major> af;
                wmma::load_matrix_sync(af, qg + (size_t)i0*256 + dk0, 256);
                wmma::fragment<wmma::matrix_b,16,16,8,wmma::precision::tf32,wmma::row_major> bf;
                wmma::load_matrix_sync(bf, Shi + dk0*SLD + j0, SLD);
                wmma::mma_sync(acc2, af, bf, acc2);
                wmma::load_matrix_sync(bf, Slo + dk0*SLD + j0, SLD);
                wmma::mma_sync(acc2, af, bf, acc2);
            }
        }
        __syncthreads();

        for (int idx = tid; idx < 1024; idx += 256){
            int r = idx >> 5, cc = idx & 31;
            float s = uh[r*SLD + cc];
            float hi = __uint_as_float(__float_as_uint(s) & 0xFFFFE000u);
            uhh[r*SLD + cc] = hi;
            uhl[r*SLD + cc] = tf32r(s - hi);
        }
        __syncthreads();

        if (warp < 4){
            #pragma unroll
            for (int t = 0; t < 8; t++){
                const int id = warp*8 + t;
                const int dk0 = (id >> 1)*16, j0 = (id & 1)*16;
                wmma::fragment<wmma::accumulator,16,16,8,float> acc;
                wmma::load_matrix_sync(acc, S + dk0*SLD + j0, SLD, wmma::mem_row_major);
                #pragma unroll
                for (int i2 = 0; i2 < 32; i2 += 8){
                    wmma::fragment<wmma::matrix_a,16,16,8,wmma::precision::tf32,wmma::col_major> af;
                    wmma::load_matrix_sync(af, kg + (size_t)i2*256 + dk0, 256);
                    wmma::fragment<wmma::matrix_b,16,16,8,wmma::precision::tf32,wmma::row_major> bf;
                    wmma::load_matrix_sync(bf, uhh + i2*SLD + j0, SLD);
                    wmma::mma_sync(acc, af, bf, acc);
                    wmma::load_matrix_sync(bf, uhl + i2*SLD + j0, SLD);
                    wmma::mma_sync(acc, af, bf, acc);
                }
                wmma::store_matrix_sync(S + dk0*SLD + j0, acc, SLD, wmma::mem_row_major);
            }
        } else {
            const int i0 = ((warp-4) & 1)*16, j0 = ((warp-4) >> 1)*16;
            #pragma unroll
            for (int i2 = 0; i2 < 32; i2 += 8){
                wmma::fragment<wmma::matrix_a,16,16,8,wmma::precision::tf32,wmma::row_major> af;
                wmma::load_matrix_sync(af, ag + i0*32 + i2, 32);
                wmma::fragment<wmma::matrix_b,16,16,8,wmma::precision::tf32,wmma::row_major> bf;
                wmma::load_matrix_sync(bf, uhh + i2*SLD + j0, SLD);
                wmma::mma_sync(acc2, af, bf, acc2);
                wmma::load_matrix_sync(bf, uhl + i2*SLD + j0, SLD);
                wmma::mma_sync(acc2, af, bf, acc2);
            }
            wmma::store_matrix_sync(og + (size_t)i0*256 + j0, acc2, 256, wmma::mem_row_major);
        }
        __syncthreads();
    }
}

// ---------------- gate heads: 2 rows per warp, weights in smem --------------
__global__ void gate_head_kernel(const float* __restrict__ z,
                                 const float* __restrict__ Wc, const float* __restrict__ bc,
                                 const float* __restrict__ Wl, const float* __restrict__ bl,
                                 const float* __restrict__ Wg, const float* __restrict__ bg,
                                 const float* __restrict__ ltc, const float* __restrict__ ltf,
                                 float* __restrict__ wgt)
{
    extern __shared__ float Ws[];   // [24][512]
    const int tid = threadIdx.x, lane = tid&31, warp = tid>>5;
    for (int idx = tid; idx < 24*128; idx += 256){
        int r = idx >> 7, c4 = (idx & 127)*4;
        const float* src = (r<8) ? Wc + r*512 + c4 :
                           (r<16)? Wl + (r-8)*512 + c4 : Wg + (r-16)*512 + c4;
        *reinterpret_cast<float4*>(&Ws[r*512 + c4]) = *reinterpret_cast<const float4*>(src);
    }
    __syncthreads();

    #pragma unroll
    for (int rr=0; rr<2; rr++){
        const int row = blockIdx.x*16 + warp*2 + rr;
        const float* zr = z + (size_t)row*512;
        float acc[24];
        #pragma unroll
        for (int r=0;r<24;r++) acc[r]=0.f;
        for (int j=lane; j<512; j+=32){
            float zv = zr[j];
            #pragma unroll
            for (int r=0;r<24;r++) acc[r] = fmaf(zv, Ws[r*512+j], acc[r]);
        }
        #pragma unroll
        for (int r=0;r<24;r++) acc[r] = warp_sum(acc[r]);

        if (lane < 4){
            const int h = lane;
            float tc = log1pf(expf(ltc[h])) + 1e-4f;
            float tf = log1pf(expf(ltf[h])) + 1e-4f;
            float c0 = acc[2*h]+bc[2*h],      c1 = acc[2*h+1]+bc[2*h+1];
            float l0 = acc[8+2*h]+bl[2*h],    l1 = acc[8+2*h+1]+bl[2*h+1];
            float g0 = acc[16+2*h]+bg[2*h],   g1 = acc[16+2*h+1]+bg[2*h+1];
            float pg0 = sigm((c0-c1)/tc), pg1 = 1.f - pg0;
            float q0  = sigm((l0-l1)/tf), q1 = 1.f - q0;
            float r0  = sigm((g0-g1)/tf), r1 = 1.f - r0;
            size_t o = (size_t)row*16 + h*4;
            wgt[o+0] = pg0*q0; wgt[o+1] = pg0*q1; wgt[o+2] = pg1*r0; wgt[o+3] = pg1*r1;
        }
    }
}

// ---------------- mix + per-head RMSNorm (rounds omix to tf32) --------------
__global__ void combine_kernel(const float* __restrict__ v, const float* __restrict__ es,
                               const float* __restrict__ el, const float* __restrict__ dl,
                               const float* __restrict__ wgt, const float* __restrict__ onw,
                               float* __restrict__ omix)
{
    const int gw = blockIdx.x*8 + (threadIdx.x>>5);
    const int row = gw >> 2, h = gw & 3;
    const int b = row >> 12, l = row & (Lq-1);
    const int lane = threadIdx.x & 31;
    const size_t gbase = ((size_t)(b*4+h)*Lq + l)*256;
    const float* wp = wgt + (size_t)row*16 + h*4;
    const float w0 = wp[0], w1 = wp[1], w2 = wp[2], w3 = wp[3];

    float4 vals[2];
    float ss = 0.f;
    #pragma unroll
    for (int s=0;s<2;s++){
        const int d = lane*4 + s*128;
        float4 a = *reinterpret_cast<const float4*>(v  + gbase + d);
        float4 b4= *reinterpret_cast<const float4*>(es + gbase + d);
        float4 c4= *reinterpret_cast<const float4*>(dl + gbase + d);
        float4 d4= *reinterpret_cast<const float4*>(el + gbase + d);
        float* av=(float*)&a; float* bv=(float*)&b4; float* cv=(float*)&c4; float* dv=(float*)&d4;
        float* ov=(float*)&vals[s];
        #pragma unroll
        for (int j=0;j<4;j++){
            float val = w0*av[j] + w1*bv[j] + w2*cv[j] + w3*dv[j];
            ov[j] = val;
            ss = fmaf(val, val, ss);
        }
    }
    ss = warp_sum(ss);
    const float rms = rsqrtf(ss*(1.f/256.f) + 1e-5f);
    float* op = omix + (size_t)row*1024 + h*256;
    #pragma unroll
    for (int s=0;s<2;s++){
        const int d = lane*4 + s*128;
        float4 w4 = *reinterpret_cast<const float4*>(onw + d);
        float* wv=(float*)&w4; float* ov=(float*)&vals[s];
        float4 r;
        float* rv=(float*)&r;
        #pragma unroll
        for (int j=0;j<4;j++) rv[j] = tf32r(ov[j]*rms*wv[j]);
        *reinterpret_cast<float4*>(op + d) = r;
    }
}

// ---------------- host ----------------
extern "C" void kernel_launch(void* const* d_in, const int* in_sizes, int n_in,
                              void* d_out, int out_size)
{
    const float* x      = (const float*)d_in[0];
    const float* Wq     = (const float*)d_in[1];
    const float* Wk     = (const float*)d_in[2];
    const float* Wv     = (const float*)d_in[3];
    const float* cqw    = (const float*)d_in[4];
    const float* ckw    = (const float*)d_in[5];
    const float* cvw    = (const float*)d_in[6];
    const float* Wb     = (const float*)d_in[7];
    const float* Wds    = (const float*)d_in[8];
    const float* bds    = (const float*)d_in[9];
    const float* Wdl    = (const float*)d_in[10];
    const float* bdl    = (const float*)d_in[11];
    const float* Wtrunk = (const float*)d_in[12];
    const float* btrunk = (const float*)d_in[13];
    const float* Wcoarse= (const float*)d_in[14];
    const float* bcoarse= (const float*)d_in[15];
    const float* Wlocal = (const float*)d_in[16];
    const float* blocal = (const float*)d_in[17];
    const float* Wglobal= (const float*)d_in[18];
    const float* bglobal= (const float*)d_in[19];
    const float* ltc    = (const float*)d_in[20];
    const float* ltf    = (const float*)d_in[21];
    const float* onw    = (const float*)d_in[22];
    const float* Wo     = (const float*)d_in[23];
    float* out = (float*)d_out;

    float* arena;
    cudaGetSymbolAddress((void**)&arena, g_arena);
    float* qpre = arena + OFF_QPRE;
    float* kpre = arena + OFF_KPRE;
    float* vpre = arena + OFF_VPRE;
    float* qb   = arena + OFF_Q;
    float* kb   = arena + OFF_K;
    float* vb   = arena + OFF_V;
    float* ub   = arena + OFF_U;
    float* wb   = arena + OFF_W;
    float* dlt  = arena + OFF_DELTA;
    float* emas = arena + OFF_EMAS;
    float* emal = arena + OFF_EMAL;
    float* omix = arena + OFF_OMIX;
    float* zb   = arena + OFF_Z;
    float* attn = arena + OFF_ATTN;
    float* beta = arena + OFF_BETA;
    float* gs   = arena + OFF_GS;
    float* gl   = arena + OFF_GL;
    float* wgt  = arena + OFF_WGT;
    float* xr   = arena + OFF_XR;
    float* WqR  = arena + OFF_WQR;
    float* WkR  = arena + OFF_WKR;
    float* WvR  = arena + OFF_WVR;
    float* WtR  = arena + OFF_WTR;
    float* WoR  = arena + OFF_WOR;

    cudaFuncSetAttribute(megagemm_kernel,  cudaFuncAttributeMaxDynamicSharedMemorySize, GEMM_SMEM_BYTES);
    cudaFuncSetAttribute(gemm_tf32_kernel, cudaFuncAttributeMaxDynamicSharedMemorySize, GEMM_SMEM_BYTES);
    cudaFuncSetAttribute(chunk_pre_kernel, cudaFuncAttributeMaxDynamicSharedMemorySize, PRE_SMEM_BYTES);
    cudaFuncSetAttribute(scan_ema_kernel,  cudaFuncAttributeMaxDynamicSharedMemorySize, SCAN_SMEM_BYTES);
    cudaFuncSetAttribute(gate_head_kernel, cudaFuncAttributeMaxDynamicSharedMemorySize, GATE_SMEM_BYTES);
    cudaFuncSetAttribute(smallproj_kernel, cudaFuncAttributeMaxDynamicSharedMemorySize, SP_SMEM_BYTES);

    dim3 blk(256);

    // tf32-round inputs once
    round_tf32_kernel<<<16384, blk>>>(x, xr, 4194304);
    round_tf32_kernel<<<1024,  blk>>>(Wq, WqR, 262144);
    round_tf32_kernel<<<1024,  blk>>>(Wk, WkR, 262144);
    round_tf32_kernel<<<1024,  blk>>>(Wv, WvR, 262144);
    round_tf32_kernel<<<512,   blk>>>(Wtrunk, WtR, 131072);
    round_tf32_kernel<<<1024,  blk>>>(Wo, WoR, 262144);

    // fused Q/K/V/trunk projections (cvt-free)
    megagemm_kernel<<<dim3(56, MROWS/GBM), blk, GEMM_SMEM_BYTES>>>(
        xr, WqR, WkR, WvR, WtR, btrunk, qpre, kpre, vpre, zb);

    // beta / decays
    smallproj_kernel<<<MROWS/16, blk, SP_SMEM_BYTES>>>(x, Wb, Wds, bds, Wdl, bdl, beta, gs, gl);

    // conv + silu + relayout
    conv_silu_kernel<<<MROWS, blk>>>(qpre, kpre, vpre, cqw, ckw, cvw, qb, kb, vb);

    // gate heads
    gate_head_kernel<<<MROWS/16, blk, GATE_SMEM_BYTES>>>(zb, Wcoarse, bcoarse, Wlocal, blocal,
                                                         Wglobal, bglobal, ltc, ltf, wgt);

    // delta rule precompute
    chunk_pre_kernel<<<2048, blk, PRE_SMEM_BYTES>>>(qb, kb, vb, beta, ub, wb, attn);

    // fused scan + EMA
    scan_ema_kernel<<<144, blk, SCAN_SMEM_BYTES>>>(qb, kb, ub, wb, attn, dlt,
                                                   vb, gs, gl, emas, emal);

    // combine + RMSNorm (rounds omix)
    combine_kernel<<<MROWS/2, blk>>>(vb, emas, emal, dlt, wgt, onw, omix);

    // output projection (cvt-free)
    gemm_tf32_kernel<<<dim3(1024/GBN, MROWS/GBM), blk, GEMM_SMEM_BYTES>>>(omix, WoR, out, 1024, 1024);
}

// round 10
// speedup vs baseline: 1.2311x; 1.0134x over previous
#include <cuda_runtime.h>
#include <math.h>
#include <mma.h>

using namespace nvcuda;

#define Hq   4
#define Lq   4096
#define Dq   1024
#define CHK  32
#define NCHK 128
#define MROWS 16384

// ---------------- scratch arena ----------------
constexpr size_t SZf      = 16777216ull;
constexpr size_t OFF_QPRE = 0;
constexpr size_t OFF_U    = 0;
constexpr size_t OFF_KPRE = SZf;
constexpr size_t OFF_W    = SZf;
constexpr size_t OFF_VPRE = 2*SZf;
constexpr size_t OFF_DELTA= 2*SZf;
constexpr size_t OFF_Q    = 3*SZf;
constexpr size_t OFF_K    = 4*SZf;
constexpr size_t OFF_V    = 5*SZf;
constexpr size_t OFF_EMAS = 6*SZf;
constexpr size_t OFF_EMAL = 7*SZf;
constexpr size_t OFF_OMIX = 8*SZf;
constexpr size_t OFF_Z    = 9*SZf;
constexpr size_t OFF_ATTN = OFF_Z + 8388608ull;
constexpr size_t OFF_BETA = OFF_ATTN + 2097152ull;
constexpr size_t OFF_GS   = OFF_BETA + 65536ull;
constexpr size_t OFF_GL   = OFF_GS + 65536ull;
constexpr size_t OFF_WGT  = OFF_GL + 65536ull;
constexpr size_t OFF_XR   = OFF_WGT + 262144ull;
constexpr size_t OFF_WQR  = OFF_XR + SZf;
constexpr size_t OFF_WKR  = OFF_WQR + 1048576ull;
constexpr size_t OFF_WVR  = OFF_WKR + 1048576ull;
constexpr size_t OFF_WTR  = OFF_WVR + 1048576ull;
constexpr size_t OFF_WOR  = OFF_WTR + 524288ull;
constexpr size_t ARENA_TOTAL = OFF_WOR + 1048576ull;

__device__ float g_arena[ARENA_TOTAL];

// chunk_pre smem
constexpr int QLD = 264;
constexpr int PRE_SMEM_FLOATS = 3*32*QLD + 3*32*36 + 32;
constexpr int PRE_SMEM_BYTES  = PRE_SMEM_FLOATS*4;        // 115328

// scan smem
constexpr int SLD = 36;
constexpr int SCAN_SMEM_FLOATS = 3*256*SLD + 3*32*SLD;
constexpr int SCAN_SMEM_BYTES  = SCAN_SMEM_FLOATS * 4;    // 124416

// GEMM tiling: 128x64, BK=32, 2-stage
constexpr int GBM = 128, GBN = 64, GBK = 32, GAP = 36;
constexpr int GSTAGE = (GBM+GBN)*GAP;
constexpr int GEMM_SMEM_BYTES = 2*GSTAGE*4;               // 55296

constexpr int GATE_SMEM_BYTES = 24*512*4;
constexpr int SP_SMEM_BYTES   = 12*1024*4;

__device__ __forceinline__ float sigm(float x){ return 1.f/(1.f+expf(-x)); }
__device__ __forceinline__ float silu(float x){ return x/(1.f+expf(-x)); }
__device__ __forceinline__ float tf32r(float x){ return wmma::__float_to_tf32(x); }

__device__ __forceinline__ float warp_sum(float v){
    #pragma unroll
    for (int o=16;o>0;o>>=1) v += __shfl_xor_sync(0xffffffffu, v, o);
    return v;
}

__device__ __forceinline__ void cp16(float* s, const float* g){
    unsigned a = (unsigned)__cvta_generic_to_shared(s);
    asm volatile("cp.async.cg.shared.global [%0], [%1], 16;" :: "r"(a), "l"(g));
}

// ---------------- fused tf32 rounding of all GEMM inputs ----------------
// segments (float4 units): x 4194304 | Wq 262144 | Wk 262144 | Wv 262144 | Wt 131072 | Wo 262144
__global__ void round_all_kernel(const float* __restrict__ x,  float* __restrict__ xr,
                                 const float* __restrict__ Wq, float* __restrict__ WqR,
                                 const float* __restrict__ Wk, float* __restrict__ WkR,
                                 const float* __restrict__ Wv, float* __restrict__ WvR,
                                 const float* __restrict__ Wt, float* __restrict__ WtR,
                                 const float* __restrict__ Wo, float* __restrict__ WoR)
{
    long i = (long)blockIdx.x*256 + threadIdx.x;
    const float* src; float* dst; long off;
    if (i < 4194304)                { src=x;  dst=xr;  off=i; }
    else if (i < 4194304+262144)    { src=Wq; dst=WqR; off=i-4194304; }
    else if (i < 4194304+2*262144)  { src=Wk; dst=WkR; off=i-4194304-262144; }
    else if (i < 4194304+3*262144)  { src=Wv; dst=WvR; off=i-4194304-2*262144; }
    else if (i < 4194304+3*262144+131072) { src=Wt; dst=WtR; off=i-4194304-3*262144; }
    else if (i < 4194304+3*262144+131072+262144) { src=Wo; dst=WoR; off=i-4194304-3*262144-131072; }
    else return;
    float4 v = reinterpret_cast<const float4*>(src)[off];
    v.x = tf32r(v.x); v.y = tf32r(v.y); v.z = tf32r(v.z); v.w = tf32r(v.w);
    reinterpret_cast<float4*>(dst)[off] = v;
}

// ---------------- GEMM core (inputs pre-rounded, NO cvt) ------------
__device__ __forceinline__ void gemm_body(const float* __restrict__ A, const float* __restrict__ W,
                                          const float* __restrict__ bias, float* __restrict__ C,
                                          int N, int K, int act, int m0, int n0, float* smem)
{
    const int tid = threadIdx.x, warp = tid>>5;
    const int tr = warp>>1, tcw = warp&1;
    const int lr = tid>>3, lc = (tid&7)*4;

    wmma::fragment<wmma::accumulator,16,16,8,float> acc[2][2];
    #pragma unroll
    for(int i=0;i<2;i++)
        #pragma unroll
        for(int j=0;j<2;j++) wmma::fill_fragment(acc[i][j], 0.f);

    const int KT = K/GBK;

    {
        float* As = smem;
        float* Ws = As + GBM*GAP;
        #pragma unroll
        for (int s=0;s<4;s++){
            int r = lr + s*32;
            cp16(&As[r*GAP+lc], &A[(size_t)(m0+r)*K + lc]);
        }
        #pragma unroll
        for (int s=0;s<2;s++){
            int r = lr + s*32;
            cp16(&Ws[r*GAP+lc], &W[(size_t)(n0+r)*K + lc]);
        }
        asm volatile("cp.async.commit_group;");
    }

    int buf = 0;
    for (int it=0; it<KT; ++it){
        if (it+1 < KT){
            float* As = smem + (buf^1)*GSTAGE;
            float* Ws = As + GBM*GAP;
            const int k0 = (it+1)*GBK;
            #pragma unroll
            for (int s=0;s<4;s++){
                int r = lr + s*32;
                cp16(&As[r*GAP+lc], &A[(size_t)(m0+r)*K + k0 + lc]);
            }
            #pragma unroll
            for (int s=0;s<2;s++){
                int r = lr + s*32;
                cp16(&Ws[r*GAP+lc], &W[(size_t)(n0+r)*K + k0 + lc]);
            }
            asm volatile("cp.async.commit_group;");
            asm volatile("cp.async.wait_group 1;");
        } else {
            asm volatile("cp.async.wait_group 0;");
        }
        __syncthreads();

        float* As = smem + buf*GSTAGE;
        float* Ws = As + GBM*GAP;
        #pragma unroll
        for (int kk=0; kk<GBK; kk+=8){
            wmma::fragment<wmma::matrix_a,16,16,8,wmma::precision::tf32,wmma::row_major> af[2];
            wmma::fragment<wmma::matrix_b,16,16,8,wmma::precision::tf32,wmma::col_major> bf[2];
            #pragma unroll
            for (int i=0;i<2;i++)
                wmma::load_matrix_sync(af[i], &As[(tr*32+i*16)*GAP + kk], GAP);
            #pragma unroll
            for (int j=0;j<2;j++)
                wmma::load_matrix_sync(bf[j], &Ws[(tcw*32+j*16)*GAP + kk], GAP);
            #pragma unroll
            for (int i=0;i<2;i++)
                #pragma unroll
                for (int j=0;j<2;j++)
                    wmma::mma_sync(acc[i][j], af[i], bf[j], acc[i][j]);
        }
        __syncthreads();
        buf ^= 1;
    }

    if (!bias && act == 0){
        #pragma unroll
        for (int i=0;i<2;i++)
            #pragma unroll
            for (int j=0;j<2;j++)
                wmma::store_matrix_sync(&C[(size_t)(m0+tr*32+i*16)*N + n0 + tcw*32 + j*16],
                                        acc[i][j], N, wmma::mem_row_major);
        return;
    }

    float* Cs = smem;
    #pragma unroll
    for (int i=0;i<2;i++)
        #pragma unroll
        for (int j=0;j<2;j++)
            wmma::store_matrix_sync(&Cs[(tr*32+i*16)*72 + tcw*32 + j*16], acc[i][j], 72, wmma::mem_row_major);
    __syncthreads();

    for (int idx = tid; idx < GBM*GBN/4; idx += 256){
        int row = idx >> 4, col = (idx & 15)*4;
        float4 v4 = *reinterpret_cast<float4*>(&Cs[row*72 + col]);
        float* vv = (float*)&v4;
        #pragma unroll
        for (int j=0;j<4;j++){
            float v = vv[j];
            if (bias) v += bias[n0+col+j];
            if (act==1) v = v/(1.f+expf(-v));
            vv[j] = v;
        }
        *reinterpret_cast<float4*>(&C[(size_t)(m0+row)*N + n0+col]) = v4;
    }
}

// ---------------- mega GEMM ----------
__global__ void megagemm_kernel(const float* __restrict__ x,
                                const float* __restrict__ Wq, const float* __restrict__ Wk,
                                const float* __restrict__ Wv, const float* __restrict__ Wt,
                                const float* __restrict__ bt,
                                float* __restrict__ qpre, float* __restrict__ kpre,
                                float* __restrict__ vpre, float* __restrict__ zb)
{
    extern __shared__ float smem[];
    const int bx = blockIdx.x;
    const int m0 = blockIdx.y*GBM;
    const float* W; float* C; const float* bias = nullptr;
    int N, act = 0, nb;
    if (bx < 16)      { W = Wq; C = qpre; N = 1024; nb = bx; }
    else if (bx < 32) { W = Wk; C = kpre; N = 1024; nb = bx-16; }
    else if (bx < 48) { W = Wv; C = vpre; N = 1024; nb = bx-32; }
    else              { W = Wt; C = zb;   N = 512;  nb = bx-48; bias = bt; act = 1; }
    gemm_body(x, W, bias, C, N, 1024, act, m0, nb*GBN, smem);
}

__global__ void gemm_tf32_kernel(const float* __restrict__ A, const float* __restrict__ W,
                                 float* __restrict__ C, int N, int K)
{
    extern __shared__ float smem[];
    gemm_body(A, W, nullptr, C, N, K, 0, blockIdx.y*GBM, blockIdx.x*GBN, smem);
}

// ---------------- causal depthwise conv + SiLU, float4, relayout ------
__global__ void conv_silu_kernel(const float* __restrict__ qp, const float* __restrict__ kp,
                                 const float* __restrict__ vp,
                                 const float* __restrict__ wq, const float* __restrict__ wk,
                                 const float* __restrict__ wv,
                                 float* __restrict__ qo, float* __restrict__ ko,
                                 float* __restrict__ vo)
{
    const int row = blockIdx.x;
    const int d4  = threadIdx.x * 4;
    const int l = row & (Lq-1), b = row >> 12;

    float4 wq_c[4], wk_c[4], wv_c[4];
    #pragma unroll
    for (int c=0;c<4;c++){
        wq_c[c] = *reinterpret_cast<const float4*>(wq + (d4+c)*4);
        wk_c[c] = *reinterpret_cast<const float4*>(wk + (d4+c)*4);
        wv_c[c] = *reinterpret_cast<const float4*>(wv + (d4+c)*4);
    }

    float aq[4] = {0,0,0,0}, ak[4] = {0,0,0,0}, av[4] = {0,0,0,0};
    #pragma unroll
    for (int j=0;j<4;j++){
        if (l - 3 + j >= 0){
            size_t idx = (size_t)(row - 3 + j)*Dq + d4;
            float4 xq = *reinterpret_cast<const float4*>(qp + idx);
            float4 xk = *reinterpret_cast<const float4*>(kp + idx);
            float4 xv = *reinterpret_cast<const float4*>(vp + idx);
            const float* xqf = (const float*)&xq;
            const float* xkf = (const float*)&xk;
            const float* xvf = (const float*)&xv;
            #pragma unroll
            for (int c=0;c<4;c++){
                aq[c] = fmaf(xqf[c], ((const float*)&wq_c[c])[j], aq[c]);
                ak[c] = fmaf(xkf[c], ((const float*)&wk_c[c])[j], ak[c]);
                av[c] = fmaf(xvf[c], ((const float*)&wv_c[c])[j], av[c]);
            }
        }
    }
    const int h = d4 >> 8, dk = d4 & 255;
    size_t o = ((size_t)(b*Hq + h)*Lq + l)*256 + dk;
    float4 oq, ok, ov;
    float* oqf = (float*)&oq; float* okf = (float*)&ok; float* ovf = (float*)&ov;
    #pragma unroll
    for (int c=0;c<4;c++){
        oqf[c] = silu(aq[c]);
        okf[c] = silu(ak[c]);
        ovf[c] = silu(av[c]);
    }
    *reinterpret_cast<float4*>(qo + o) = oq;
    *reinterpret_cast<float4*>(ko + o) = ok;
    *reinterpret_cast<float4*>(vo + o) = ov;
}

// ---------------- beta/gs/gl: 2 rows per warp, weights in smem ----------------
__global__ void smallproj_kernel(const float* __restrict__ x,
                                 const float* __restrict__ Wb, const float* __restrict__ Wds,
                                 const float* __restrict__ bds, const float* __restrict__ Wdl,
                                 const float* __restrict__ bdl,
                                 float* __restrict__ beta, float* __restrict__ gs,
                                 float* __restrict__ gl)
{
    extern __shared__ float Ws[];
    const int tid = threadIdx.x, lane = tid&31, warp = tid>>5;
    for (int idx = tid; idx < 12*256; idx += 256){
        int r = idx >> 8, c4 = (idx & 255)*4;
        const float* src = (r<4) ? Wb + r*1024 + c4 :
                           (r<8) ? Wds + (r-4)*1024 + c4 : Wdl + (r-8)*1024 + c4;
        *reinterpret_cast<float4*>(&Ws[r*1024 + c4]) = *reinterpret_cast<const float4*>(src);
    }
    __syncthreads();

    #pragma unroll
    for (int rr=0; rr<2; rr++){
        const int row = blockIdx.x*16 + warp*2 + rr;
        const float* xr = x + (size_t)row*Dq;
        float acc[12];
        #pragma unroll
        for (int r=0;r<12;r++) acc[r]=0.f;
        for (int j=lane; j<1024; j+=32){
            float xv = xr[j];
            #pragma unroll
            for (int r=0;r<12;r++) acc[r] = fmaf(xv, Ws[r*1024+j], acc[r]);
        }
        #pragma unroll
        for (int r=0;r<12;r++) acc[r] = warp_sum(acc[r]);

        if (lane < 12){
            const int h = lane & 3;
            const int b = row >> 12, l = row & (Lq-1);
            size_t o = (size_t)(b*4 + h)*Lq + l;
            if (lane < 4)      beta[o] = sigm(acc[h]);
            else if (lane < 8) gs[o]   = sigm(acc[4+h] + bds[h]);
            else               gl[o]   = sigm(acc[8+h] + bdl[h]);
        }
    }
}

// ---------------- delta-rule per-chunk precompute (wmma) -------
// writes: q,k normalized+rounded; u (fp32); w = round(-(Ti*beta)@k) ; attn rounded
__global__ void chunk_pre_kernel(float* __restrict__ q, float* __restrict__ k,
                                 const float* __restrict__ v, const float* __restrict__ beta,
                                 float* __restrict__ u, float* __restrict__ w,
                                 float* __restrict__ attn)
{
    extern __shared__ float sm[];
    float* qs  = sm;
    float* ks  = qs + 32*QLD;
    float* vs  = ks + 32*QLD;
    float* att = vs + 32*QLD;
    float* Lm  = att+ 32*36;
    float* Ti  = Lm + 32*36;
    float* bs  = Ti + 32*36;
    const int bh = blockIdx.x >> 7, c = blockIdx.x & 127;
    const int tid = threadIdx.x, lane = tid&31, wid = tid>>5;
    const size_t base = (size_t)bh*Lq + (size_t)c*CHK;

    for (int idx = tid; idx < 32*64; idx += 256){
        int i = idx >> 6, d4 = (idx & 63)*4;
        size_t g = (base+i)*256 + d4;
        *reinterpret_cast<float4*>(&qs[i*QLD+d4]) = *reinterpret_cast<const float4*>(&q[g]);
        *reinterpret_cast<float4*>(&ks[i*QLD+d4]) = *reinterpret_cast<const float4*>(&k[g]);
        *reinterpret_cast<float4*>(&vs[i*QLD+d4]) = *reinterpret_cast<const float4*>(&v[g]);
    }
    if (tid < 32) bs[tid] = beta[base + tid];
    __syncthreads();

    #pragma unroll
    for (int r=0;r<4;r++){
        int i = wid*4 + r;
        float sq=0.f, sk=0.f;
        for (int d=lane; d<256; d+=32){
            float a=qs[i*QLD+d]; sq=fmaf(a,a,sq);
            float bb=ks[i*QLD+d]; sk=fmaf(bb,bb,sk);
        }
        sq = warp_sum(sq); sk = warp_sum(sk);
        float rq = rsqrtf(sq + 1e-6f), rk = rsqrtf(sk + 1e-6f);
        for (int d=lane; d<256; d+=32){
            qs[i*QLD+d] = tf32r(qs[i*QLD+d]*rq);
            ks[i*QLD+d] = tf32r(ks[i*QLD+d]*rk);
        }
    }
    __syncthreads();

    for (int idx = tid; idx < 32*64; idx += 256){
        int i = idx>>6, d4 = (idx&63)*4;
        size_t g = (base+i)*256 + d4;
        *reinterpret_cast<float4*>(&q[g]) = *reinterpret_cast<float4*>(&qs[i*QLD+d4]);
        *reinterpret_cast<float4*>(&k[g]) = *reinterpret_cast<float4*>(&ks[i*QLD+d4]);
        float b = bs[i];
        float4 vv = *reinterpret_cast<float4*>(&vs[i*QLD+d4]);
        vv.x = tf32r(vv.x*b); vv.y = tf32r(vv.y*b); vv.z = tf32r(vv.z*b); vv.w = tf32r(vv.w*b);
        *reinterpret_cast<float4*>(&vs[i*QLD+d4]) = vv;
    }
    __syncthreads();

    {
        const int ww = wid & 3;
        const int j0 = (ww & 1)*16, i0 = (ww >> 1)*16;
        const float* Asrc = (wid < 4) ? qs : ks;
        float* dst = (wid < 4) ? att : Lm;
        wmma::fragment<wmma::accumulator,16,16,8,float> acc;
        wmma::fill_fragment(acc, 0.f);
        #pragma unroll 4
        for (int dk0 = 0; dk0 < 256; dk0 += 8){
            wmma::fragment<wmma::matrix_a,16,16,8,wmma::precision::tf32,wmma::row_major> af;
            wmma::load_matrix_sync(af, Asrc + i0*QLD + dk0, QLD);
            wmma::fragment<wmma::matrix_b,16,16,8,wmma::precision::tf32,wmma::col_major> bf;
            wmma::load_matrix_sync(bf, ks + j0*QLD + dk0, QLD);
            wmma::mma_sync(acc, af, bf, acc);
        }
        wmma::store_matrix_sync(dst + i0*36 + j0, acc, 36, wmma::mem_row_major);
    }
    __syncthreads();

    for (int idx = tid; idx < 1024; idx += 256){
        int i = idx>>5, j = idx&31;
        attn[(size_t)blockIdx.x*1024 + idx] = (j <= i) ? tf32r(att[i*36+j]) : 0.f;
        Lm[i*36+j] = (j < i) ? bs[i]*Lm[i*36+j] : 0.f;
    }
    __syncthreads();

    if (wid == 0){
        for (int i=0;i<32;i++){
            float xv = (lane==i) ? 1.f : 0.f;
            for (int p=0;p<i;p++) xv = fmaf(-Lm[i*36+p], Ti[p*36+lane], xv);
            Ti[i*36+lane] = xv;
            __syncwarp();
        }
    }
    __syncthreads();

    // Lm <- round(Ti) ; att <- -round(Ti*beta[col])  (negated so stored w = -w_orig)
    for (int idx = tid; idx < 1024; idx += 256){
        int i = idx>>5, j = idx&31;
        float t = Ti[i*36+j];
        Lm[i*36+j]  = tf32r(t);
        att[i*36+j] = -tf32r(t*bs[j]);
    }
    __syncthreads();

    // u = Ti@vs (global, fp32) ; wneg = (-Tib)@ks -> qs smem (for rounding pass)
    #pragma unroll
    for (int t = 0; t < 8; t++){
        const int id = wid*8 + t;
        const bool isU = id < 32;
        const int tile = isU ? id : id - 32;
        const int i0 = (tile & 1)*16;
        const int j0 = (tile >> 1)*16;
        const float* A = isU ? Lm : att;
        const float* B = isU ? vs : ks;
        wmma::fragment<wmma::accumulator,16,16,8,float> acc;
        wmma::fill_fragment(acc, 0.f);
        #pragma unroll
        for (int m0 = 0; m0 < 32; m0 += 8){
            wmma::fragment<wmma::matrix_a,16,16,8,wmma::precision::tf32,wmma::row_major> af;
            wmma::load_matrix_sync(af, A + i0*36 + m0, 36);
            wmma::fragment<wmma::matrix_b,16,16,8,wmma::precision::tf32,wmma::row_major> bf;
            wmma::load_matrix_sync(bf, B + m0*QLD + j0, QLD);
            wmma::mma_sync(acc, af, bf, acc);
        }
        if (isU)
            wmma::store_matrix_sync(u + (base+i0)*256 + j0, acc, 256, wmma::mem_row_major);
        else
            wmma::store_matrix_sync(qs + i0*QLD + j0, acc, QLD, wmma::mem_row_major);
    }
    __syncthreads();

    // round w (already negated) and store to global
    for (int idx = tid; idx < 32*64; idx += 256){
        int i = idx>>6, d4 = (idx&63)*4;
        float4 vv = *reinterpret_cast<float4*>(&qs[i*QLD+d4]);
        vv.x = tf32r(vv.x); vv.y = tf32r(vv.y); vv.z = tf32r(vv.z); vv.w = tf32r(vv.w);
        *reinterpret_cast<float4*>(&w[(base+i)*256 + d4]) = vv;
    }
}

// ---------------- fused: delta-scan (0-127) + dual EMA (128-143) ----
// w input is pre-negated and pre-rounded; q,k,attn pre-rounded.
__global__ void scan_ema_kernel(const float* __restrict__ q, const float* __restrict__ k,
                                const float* __restrict__ u, const float* __restrict__ w,
                                const float* __restrict__ attn, float* __restrict__ o,
                                const float* __restrict__ v, const float* __restrict__ gs,
                                const float* __restrict__ gl,
                                float* __restrict__ es, float* __restrict__ el)
{
    if (blockIdx.x >= 128){
        const int bh = blockIdx.x - 128;
        const int dv = threadIdx.x;
        const size_t vbase = (size_t)bh*Lq*256 + dv;
        const float* gsp = gs + (size_t)bh*Lq;
        const float* glp = gl + (size_t)bh*Lq;
        float ss = 0.f, sl = 0.f;
        #pragma unroll 8
        for (int t=0;t<Lq;t++){
            float vv = v[vbase + (size_t)t*256];
            float a = gsp[t], b2 = glp[t];
            ss = fmaf(a, ss, (1.f-a)*vv);
            sl = fmaf(b2, sl, (1.f-b2)*vv);
            es[vbase + (size_t)t*256] = ss;
            el[vbase + (size_t)t*256] = sl;
        }
        return;
    }

    extern __shared__ float sm[];
    float* S   = sm;
    float* Shi = S   + 256*SLD;
    float* Slo = Shi + 256*SLD;
    float* uh  = Slo + 256*SLD;
    float* uhh = uh  + 32*SLD;
    float* uhl = uhh + 32*SLD;
    const int bh = blockIdx.x >> 3;
    const int d0 = (blockIdx.x & 7) * 32;
    const int tid = threadIdx.x, warp = tid >> 5;

    for (int i = tid; i < 3*256*SLD; i += 256) sm[i] = 0.f;
    __syncthreads();

    wmma::fragment<wmma::accumulator,16,16,8,float> acc2;

    for (int c = 0; c < NCHK; ++c){
        const size_t base = (size_t)bh*Lq + (size_t)c*32;
        const float* qg = q + base*256;
        const float* kg = k + base*256;
        const float* wg = w + base*256;
        const float* ug = u + base*256 + d0;
        const float* ag = attn + ((size_t)bh*NCHK + c)*1024;
        float*       og = o + base*256 + d0;

        for (int idx = tid; idx < 256*32; idx += 256){
            int r = idx >> 5, cc = idx & 31;
            float s = S[r*SLD + cc];
            float hi = __uint_as_float(__float_as_uint(s) & 0xFFFFE000u);
            Shi[r*SLD + cc] = hi;
            Slo[r*SLD + cc] = tf32r(s - hi);
        }
        __syncthreads();

        if (warp < 4){
            // uh = u + wneg @ (Shi + Slo)   (w pre-negated, no cvt)
            const int i0 = (warp & 1)*16, j0 = (warp >> 1)*16;
            wmma::fragment<wmma::accumulator,16,16,8,float> acc;
            wmma::load_matrix_sync(acc, ug + (size_t)i0*256 + j0, 256, wmma::mem_row_major);
            #pragma unroll 4
            for (int dk0 = 0; dk0 < 256; dk0 += 8){
                wmma::fragment<wmma::matrix_a,16,16,8,wmma::precision::tf32,wmma::row_major> af;
                wmma::load_matrix_sync(af, wg + (size_t)i0*256 + dk0, 256);
                wmma::fragment<wmma::matrix_b,16,16,8,wmma::precision::tf32,wmma::row_major> bf;
                wmma::load_matrix_sync(bf, Shi + dk0*SLD + j0, SLD);
                wmma::mma_sync(acc, af, bf, acc);
                wmma::load_matrix_sync(bf, Slo + dk0*SLD + j0, SLD);
                wmma::mma_sync(acc, af, bf, acc);
            }
            wmma::store_matrix_sync(uh + i0*SLD + j0, acc, SLD, wmma::mem_row_major);
        } else {
            // q @ Shi only (output path)
            const int i0 = ((warp-4) & 1)*16, j0 = ((warp-4) >> 1)*16;
            wmma::fill_fragment(acc2, 0.f);
            #pragma unroll 4
            for (int dk0 = 0; dk0 < 256; dk0 += 8){
                wmma::fragment<wmma::matrix_a,16,16,8,wmma::precision::tf32,wmma::row_major> af;
                wmma::load_matrix_sync(af, qg + (size_t)i0*256 + dk0, 256);
                wmma::fragment<wmma::matrix_b,16,16,8,wmma::precision::tf32,wmma::row_major> bf;
                wmma::load_matrix_sync(bf, Shi + dk0*SLD + j0, SLD);
                wmma::mma_sync(acc2, af, bf, acc2);
            }
        }
        __syncthreads();

        for (int idx = tid; idx < 1024; idx += 256){
            int r = idx >> 5, cc = idx & 31;
            float s = uh[r*SLD + cc];
            float hi = __uint_as_float(__float_as_uint(s) & 0xFFFFE000u);
            uhh[r*SLD + cc] = hi;
            uhl[r*SLD + cc] = tf32r(s - hi);
        }
        __syncthreads();

        if (warp < 4){
            #pragma unroll
            for (int t = 0; t < 8; t++){
                const int id = warp*8 + t;
                const int dk0 = (id >> 1)*16, j0 = (id & 1)*16;
                wmma::fragment<wmma::accumulator,16,16,8,float> acc;
                wmma::load_matrix_sync(acc, S + dk0*SLD + j0, SLD, wmma::mem_row_major);
                #pragma unroll
                for (int i2 = 0; i2 < 32; i2 += 8){
                    wmma::fragment<wmma::matrix_a,16,16,8,wmma::precision::tf32,wmma::col_major> af;
                    wmma::load_matrix_sync(af, kg + (size_t)i2*256 + dk0, 256);
                    wmma::fragment<wmma::matrix_b,16,16,8,wmma::precision::tf32,wmma::row_major> bf;
                    wmma::load_matrix_sync(bf, uhh + i2*SLD + j0, SLD);
                    wmma::mma_sync(acc, af, bf, acc);
                    wmma::load_matrix_sync(bf, uhl + i2*SLD + j0, SLD);
                    wmma::mma_sync(acc, af, bf, acc);
                }
                wmma::store_matrix_sync(S + dk0*SLD + j0, acc, SLD, wmma::mem_row_major);
            }
        } else {
            const int i0 = ((warp-4) & 1)*16, j0 = ((warp-4) >> 1)*16;
            #pragma unroll
            for (int i2 = 0; i2 < 32; i2 += 8){
                wmma::fragment<wmma::matrix_a,16,16,8,wmma::precision::tf32,wmma::row_major> af;
                wmma::load_matrix_sync(af, ag + i0*32 + i2, 32);
                wmma::fragment<wmma::matrix_b,16,16,8,wmma::precision::tf32,wmma::row_major> bf;
                wmma::load_matrix_sync(bf, uhh + i2*SLD + j0, SLD);
                wmma::mma_sync(acc2, af, bf, acc2);
                wmma::load_matrix_sync(bf, uhl + i2*SLD + j0, SLD);
                wmma::mma_sync(acc2, af, bf, acc2);
            }
            wmma::store_matrix_sync(og + (size_t)i0*256 + j0, acc2, 256, wmma::mem_row_major);
        }
        __syncthreads();
    }
}

// ---------------- gate heads: 2 rows per warp, weights in smem --------------
__global__ void gate_head_kernel(const float* __restrict__ z,
                                 const float* __restrict__ Wc, const float* __restrict__ bc,
                                 const float* __restrict__ Wl, const float* __restrict__ bl,
                                 const float* __restrict__ Wg, const float* __restrict__ bg,
                                 const float* __restrict__ ltc, const float* __restrict__ ltf,
                                 float* __restrict__ wgt)
{
    extern __shared__ float Ws[];
    const int tid = threadIdx.x, lane = tid&31, warp = tid>>5;
    for (int idx = tid; idx < 24*128; idx += 256){
        int r = idx >> 7, c4 = (idx & 127)*4;
        const float* src = (r<8) ? Wc + r*512 + c4 :
                           (r<16)? Wl + (r-8)*512 + c4 : Wg + (r-16)*512 + c4;
        *reinterpret_cast<float4*>(&Ws[r*512 + c4]) = *reinterpret_cast<const float4*>(src);
    }
    __syncthreads();

    #pragma unroll
    for (int rr=0; rr<2; rr++){
        const int row = blockIdx.x*16 + warp*2 + rr;
        const float* zr = z + (size_t)row*512;
        float acc[24];
        #pragma unroll
        for (int r=0;r<24;r++) acc[r]=0.f;
        for (int j=lane; j<512; j+=32){
            float zv = zr[j];
            #pragma unroll
            for (int r=0;r<24;r++) acc[r] = fmaf(zv, Ws[r*512+j], acc[r]);
        }
        #pragma unroll
        for (int r=0;r<24;r++) acc[r] = warp_sum(acc[r]);

        if (lane < 4){
            const int h = lane;
            float tc = log1pf(expf(ltc[h])) + 1e-4f;
            float tf = log1pf(expf(ltf[h])) + 1e-4f;
            float c0 = acc[2*h]+bc[2*h],      c1 = acc[2*h+1]+bc[2*h+1];
            float l0 = acc[8+2*h]+bl[2*h],    l1 = acc[8+2*h+1]+bl[2*h+1];
            float g0 = acc[16+2*h]+bg[2*h],   g1 = acc[16+2*h+1]+bg[2*h+1];
            float pg0 = sigm((c0-c1)/tc), pg1 = 1.f - pg0;
            float q0  = sigm((l0-l1)/tf), q1 = 1.f - q0;
            float r0  = sigm((g0-g1)/tf), r1 = 1.f - r0;
            size_t o = (size_t)row*16 + h*4;
            wgt[o+0] = pg0*q0; wgt[o+1] = pg0*q1; wgt[o+2] = pg1*r0; wgt[o+3] = pg1*r1;
        }
    }
}

// ---------------- mix + per-head RMSNorm (rounds omix to tf32) --------------
__global__ void combine_kernel(const float* __restrict__ v, const float* __restrict__ es,
                               const float* __restrict__ el, const float* __restrict__ dl,
                               const float* __restrict__ wgt, const float* __restrict__ onw,
                               float* __restrict__ omix)
{
    const int gw = blockIdx.x*8 + (threadIdx.x>>5);
    const int row = gw >> 2, h = gw & 3;
    const int b = row >> 12, l = row & (Lq-1);
    const int lane = threadIdx.x & 31;
    const size_t gbase = ((size_t)(b*4+h)*Lq + l)*256;
    const float* wp = wgt + (size_t)row*16 + h*4;
    const float w0 = wp[0], w1 = wp[1], w2 = wp[2], w3 = wp[3];

    float4 vals[2];
    float ss = 0.f;
    #pragma unroll
    for (int s=0;s<2;s++){
        const int d = lane*4 + s*128;
        float4 a = *reinterpret_cast<const float4*>(v  + gbase + d);
        float4 b4= *reinterpret_cast<const float4*>(es + gbase + d);
        float4 c4= *reinterpret_cast<const float4*>(dl + gbase + d);
        float4 d4= *reinterpret_cast<const float4*>(el + gbase + d);
        float* av=(float*)&a; float* bv=(float*)&b4; float* cv=(float*)&c4; float* dv=(float*)&d4;
        float* ov=(float*)&vals[s];
        #pragma unroll
        for (int j=0;j<4;j++){
            float val = w0*av[j] + w1*bv[j] + w2*cv[j] + w3*dv[j];
            ov[j] = val;
            ss = fmaf(val, val, ss);
        }
    }
    ss = warp_sum(ss);
    const float rms = rsqrtf(ss*(1.f/256.f) + 1e-5f);
    float* op = omix + (size_t)row*1024 + h*256;
    #pragma unroll
    for (int s=0;s<2;s++){
        const int d = lane*4 + s*128;
        float4 w4 = *reinterpret_cast<const float4*>(onw + d);
        float* wv=(float*)&w4; float* ov=(float*)&vals[s];
        float4 r;
        float* rv=(float*)&r;
        #pragma unroll
        for (int j=0;j<4;j++) rv[j] = tf32r(ov[j]*rms*wv[j]);
        *reinterpret_cast<float4*>(op + d) = r;
    }
}

// ---------------- host ----------------
extern "C" void kernel_launch(void* const* d_in, const int* in_sizes, int n_in,
                              void* d_out, int out_size)
{
    const float* x      = (const float*)d_in[0];
    const float* Wq     = (const float*)d_in[1];
    const float* Wk     = (const float*)d_in[2];
    const float* Wv     = (const float*)d_in[3];
    const float* cqw    = (const float*)d_in[4];
    const float* ckw    = (const float*)d_in[5];
    const float* cvw    = (const float*)d_in[6];
    const float* Wb     = (const float*)d_in[7];
    const float* Wds    = (const float*)d_in[8];
    const float* bds    = (const float*)d_in[9];
    const float* Wdl    = (const float*)d_in[10];
    const float* bdl    = (const float*)d_in[11];
    const float* Wtrunk = (const float*)d_in[12];
    const float* btrunk = (const float*)d_in[13];
    const float* Wcoarse= (const float*)d_in[14];
    const float* bcoarse= (const float*)d_in[15];
    const float* Wlocal = (const float*)d_in[16];
    const float* blocal = (const float*)d_in[17];
    const float* Wglobal= (const float*)d_in[18];
    const float* bglobal= (const float*)d_in[19];
    const float* ltc    = (const float*)d_in[20];
    const float* ltf    = (const float*)d_in[21];
    const float* onw    = (const float*)d_in[22];
    const float* Wo     = (const float*)d_in[23];
    float* out = (float*)d_out;

    float* arena;
    cudaGetSymbolAddress((void**)&arena, g_arena);
    float* qpre = arena + OFF_QPRE;
    float* kpre = arena + OFF_KPRE;
    float* vpre = arena + OFF_VPRE;
    float* qb   = arena + OFF_Q;
    float* kb   = arena + OFF_K;
    float* vb   = arena + OFF_V;
    float* ub   = arena + OFF_U;
    float* wb   = arena + OFF_W;
    float* dlt  = arena + OFF_DELTA;
    float* emas = arena + OFF_EMAS;
    float* emal = arena + OFF_EMAL;
    float* omix = arena + OFF_OMIX;
    float* zb   = arena + OFF_Z;
    float* attn = arena + OFF_ATTN;
    float* beta = arena + OFF_BETA;
    float* gs   = arena + OFF_GS;
    float* gl   = arena + OFF_GL;
    float* wgt  = arena + OFF_WGT;
    float* xr   = arena + OFF_XR;
    float* WqR  = arena + OFF_WQR;
    float* WkR  = arena + OFF_WKR;
    float* WvR  = arena + OFF_WVR;
    float* WtR  = arena + OFF_WTR;
    float* WoR  = arena + OFF_WOR;

    cudaFuncSetAttribute(megagemm_kernel,  cudaFuncAttributeMaxDynamicSharedMemorySize, GEMM_SMEM_BYTES);
    cudaFuncSetAttribute(gemm_tf32_kernel, cudaFuncAttributeMaxDynamicSharedMemorySize, GEMM_SMEM_BYTES);
    cudaFuncSetAttribute(chunk_pre_kernel, cudaFuncAttributeMaxDynamicSharedMemorySize, PRE_SMEM_BYTES);
    cudaFuncSetAttribute(scan_ema_kernel,  cudaFuncAttributeMaxDynamicSharedMemorySize, SCAN_SMEM_BYTES);
    cudaFuncSetAttribute(gate_head_kernel, cudaFuncAttributeMaxDynamicSharedMemorySize, GATE_SMEM_BYTES);
    cudaFuncSetAttribute(smallproj_kernel, cudaFuncAttributeMaxDynamicSharedMemorySize, SP_SMEM_BYTES);

    dim3 blk(256);

    // 0: fused rounding of all GEMM inputs (5374208 float4s)
    round_all_kernel<<<20993, blk>>>(x, xr, Wq, WqR, Wk, WkR, Wv, WvR, Wtrunk, WtR, Wo, WoR);

    // 1: fused Q/K/V/trunk projections
    megagemm_kernel<<<dim3(56, MROWS/GBM), blk, GEMM_SMEM_BYTES>>>(
        xr, WqR, WkR, WvR, WtR, btrunk, qpre, kpre, vpre, zb);

    // 2: conv + silu + relayout
    conv_silu_kernel<<<MROWS, blk>>>(qpre, kpre, vpre, cqw, ckw, cvw, qb, kb, vb);

    // 3: beta / decays
    smallproj_kernel<<<MROWS/16, blk, SP_SMEM_BYTES>>>(x, Wb, Wds, bds, Wdl, bdl, beta, gs, gl);

    // 4: delta rule precompute
    chunk_pre_kernel<<<2048, blk, PRE_SMEM_BYTES>>>(qb, kb, vb, beta, ub, wb, attn);

    // 5: fused scan + EMA  (profiled by ncu -s 5)
    scan_ema_kernel<<<144, blk, SCAN_SMEM_BYTES>>>(qb, kb, ub, wb, attn, dlt,
                                                   vb, gs, gl, emas, emal);

    // 6: gate heads
    gate_head_kernel<<<MROWS/16, blk, GATE_SMEM_BYTES>>>(zb, Wcoarse, bcoarse, Wlocal, blocal,
                                                         Wglobal, bglobal, ltc, ltf, wgt);

    // 7: combine + RMSNorm
    combine_kernel<<<MROWS/2, blk>>>(vb, emas, emal, dlt, wgt, onw, omix);

    // 8: output projection
    gemm_tf32_kernel<<<dim3(1024/GBN, MROWS/GBM), blk, GEMM_SMEM_BYTES>>>(omix, WoR, out, 1024, 1024);
}